// round 1
// baseline (speedup 1.0000x reference)
#include <cuda_runtime.h>
#include <math.h>

#define BB   8
#define CI   64
#define CO   64
#define HH   128
#define WW   128
#define CTXC 16
#define FF   576            // CI * 9
#define HWSZ (HH*WW)

#define TILE_H 4
#define TILE_W 64
#define HALO_W (TILE_W + 2)     // 66
#define HALO_H (TILE_H + 2)     // 6
#define HALO_N (HALO_H * HALO_W) // 396
#define WPAD 18                 // wsm row stride (16 o + 2 pad)

// ---- device scratch (no allocation allowed) ----
__device__ float g_meanx[BB * CI];
__device__ float g_ctx[BB * CTXC];
__device__ float g_weff[BB * CO * FF];   // [b][o][cin*9+kk], value_w folded in

// ================= kernel 1: spatial mean of x -> (B, C) =================
__global__ void k_mean(const float* __restrict__ x) {
    int bc = blockIdx.x;  // 0..511
    const float4* p4 = (const float4*)(x + (size_t)bc * HWSZ);
    float s = 0.f;
    for (int i = threadIdx.x; i < HWSZ / 4; i += 256) {
        float4 v = p4[i];
        s += (v.x + v.y) + (v.z + v.w);
    }
    __shared__ float red[8];
#pragma unroll
    for (int o = 16; o; o >>= 1) s += __shfl_xor_sync(0xffffffffu, s, o);
    if ((threadIdx.x & 31) == 0) red[threadIdx.x >> 5] = s;
    __syncthreads();
    if (threadIdx.x < 8) {
        s = red[threadIdx.x];
#pragma unroll
        for (int o = 4; o; o >>= 1) s += __shfl_xor_sync(0xffu, s, o);
        if (threadIdx.x == 0) g_meanx[bc] = s * (1.f / (float)HWSZ);
    }
}

// ================= kernel 2: ctx_vec = meanx @ ctx_w^T + ctx_b =================
__global__ void k_ctx(const float* __restrict__ ctx_w, const float* __restrict__ ctx_b) {
    int t = threadIdx.x;
    if (t >= BB * CTXC) return;
    int b = t >> 4, o = t & 15;
    float s = ctx_b[o];
#pragma unroll 8
    for (int c = 0; c < CI; c++) s += ctx_w[o * CI + c] * g_meanx[b * CI + c];
    g_ctx[t] = s;   // t == b*16 + o
}

// ====== kernel 3: generate per-sample kernels, center, fold in value_w ======
// one block per (b, o); 192 threads, 3 f-elements each (f = cin*9 + kk)
__global__ void k_gen(const float* __restrict__ kg_w, const float* __restrict__ kg_b,
                      const float* __restrict__ gamma, const float* __restrict__ value_w) {
    int bo = blockIdx.x;          // 0..511
    int b = bo >> 6, o = bo & 63;
    __shared__ float ctx_s[CTXC];
    __shared__ float kern_s[FF];
    __shared__ float vw_s[CI * CI];
    __shared__ float red[6];
    int t = threadIdx.x;          // 0..191
    if (t < CTXC) ctx_s[t] = g_ctx[b * CTXC + t];
    for (int i = t; i < CI * CI; i += 192) vw_s[i] = value_w[i];
    __syncthreads();

    float part = 0.f;
#pragma unroll
    for (int i = 0; i < 3; i++) {
        int f = t + 192 * i;                       // = c*9 + kk
        // flat kernel index kf = (o*CI + c)*9 + kk = o*FF + f
        const float4* wr = (const float4*)(kg_w + (size_t)(o * FF + f) * 16);
        float s = kg_b[o * FF + f];
#pragma unroll
        for (int jj = 0; jj < 4; jj++) {
            float4 w = wr[jj];
            s += ctx_s[4 * jj + 0] * w.x + ctx_s[4 * jj + 1] * w.y
               + ctx_s[4 * jj + 2] * w.z + ctx_s[4 * jj + 3] * w.w;
        }
        s = tanhf(s);
        kern_s[f] = s;
        part += s;
    }
#pragma unroll
    for (int off = 16; off; off >>= 1) part += __shfl_xor_sync(0xffffffffu, part, off);
    if ((t & 31) == 0) red[t >> 5] = part;
    __syncthreads();   // also makes kern_s visible
    float total = red[0] + red[1] + red[2] + red[3] + red[4] + red[5];
    float lam = 1.f / (1.f + __expf(-gamma[o]));
    float sub = lam * total * (1.f / (float)FF);

    // W_eff[b][o][cin][kk] = sum_cp (kern[cp][kk] - sub) * value_w[cp][cin]
#pragma unroll
    for (int i = 0; i < 3; i++) {
        int f = t + 192 * i;
        int cin = f / 9, kk = f % 9;
        float s = 0.f;
#pragma unroll 16
        for (int cp = 0; cp < CI; cp++)
            s += (kern_s[cp * 9 + kk] - sub) * vw_s[cp * CI + cin];
        g_weff[(size_t)bo * FF + f] = s;
    }
}

// ================= kernel 4: dynamic 3x3 conv, direct, fp32 =================
// block: 16 output channels x (4 x 64) spatial tile; 256 threads;
// per thread: 4 o x 4 rows (fixed column g). Double-buffered x halo in smem.
__global__ void __launch_bounds__(256, 3)
k_conv(const float* __restrict__ x, const float* __restrict__ bias,
       float* __restrict__ out) {
    __shared__ float wsm[FF * WPAD];        // [f][ol], ol in 0..15, padded
    __shared__ float xs[2 * HALO_N];        // double-buffered halo

    int t = threadIdx.x;
    int b  = blockIdx.z;          // 0..7
    int og = blockIdx.y;          // 0..3  -> o0 = og*16
    int ty = blockIdx.x >> 1;     // 0..31
    int tx = blockIdx.x & 1;      // 0..1
    int y0 = ty * TILE_H;
    int x0 = tx * TILE_W;
    int om = t & 3;               // o sub-group (4 o's each)
    int g  = t >> 2;              // column within tile, 0..63

    // ---- stage W_eff slice (16 o x 576 f), transposed into wsm[f*WPAD + ol] ----
    const float4* wg = (const float4*)(g_weff + (size_t)(b * CO + og * 16) * FF);
    for (int v = t; v < 16 * 144; v += 256) {
        int ol = v / 144;
        int f4 = v % 144;
        float4 w4 = wg[(size_t)ol * 144 + f4];
        int f = 4 * f4;
        wsm[(f + 0) * WPAD + ol] = w4.x;
        wsm[(f + 1) * WPAD + ol] = w4.y;
        wsm[(f + 2) * WPAD + ol] = w4.z;
        wsm[(f + 3) * WPAD + ol] = w4.w;
    }

    // ---- halo loader setup: elements t and t+256 ----
    int e0 = t;
    int hr0 = e0 / HALO_W, hc0 = e0 % HALO_W;
    int gy0 = y0 - 1 + hr0, gx0 = x0 - 1 + hc0;
    bool v0 = (gy0 >= 0) && (gy0 < HH) && (gx0 >= 0) && (gx0 < WW);
    long off0 = ((long)(b * CI) * HH + gy0) * WW + gx0;   // channel 0

    int e1 = t + 256;
    bool has1 = (e1 < HALO_N);
    int hr1 = e1 / HALO_W, hc1 = e1 % HALO_W;
    int gy1 = y0 - 1 + hr1, gx1 = x0 - 1 + hc1;
    bool v1 = has1 && (gy1 >= 0) && (gy1 < HH) && (gx1 >= 0) && (gx1 < WW);
    long off1 = ((long)(b * CI) * HH + gy1) * WW + gx1;

    float acc[4][4];
#pragma unroll
    for (int i = 0; i < 4; i++)
#pragma unroll
        for (int r = 0; r < 4; r++) acc[i][r] = 0.f;

    // preload channel 0 halo into buffer 0
    {
        float n0 = v0 ? x[off0] : 0.f;
        xs[e0] = n0;
        if (has1) xs[e1] = v1 ? x[off1] : 0.f;
    }
    __syncthreads();

    int wb = 4 * om;
    for (int c = 0; c < CI; c++) {
        // prefetch next channel's halo into registers (overlaps compute)
        float n0 = 0.f, n1 = 0.f;
        if (c + 1 < CI) {
            long coff = (long)(c + 1) * HWSZ;
            if (v0) n0 = x[off0 + coff];
            if (v1) n1 = x[off1 + coff];
        }

        const float* cb = xs + (c & 1) * HALO_N;
        const float* wrow = wsm + c * 9 * WPAD + wb;

        // hoist the 6x3 x-window this thread needs
        float xv[6][3];
#pragma unroll
        for (int rr = 0; rr < 6; rr++)
#pragma unroll
            for (int cc = 0; cc < 3; cc++)
                xv[rr][cc] = cb[rr * HALO_W + g + cc];

#pragma unroll
        for (int kk = 0; kk < 9; kk++) {
            int kh = kk / 3, kw = kk % 3;
            float a0 = wrow[kk * WPAD + 0];
            float a1 = wrow[kk * WPAD + 1];
            float a2 = wrow[kk * WPAD + 2];
            float a3 = wrow[kk * WPAD + 3];
#pragma unroll
            for (int r = 0; r < 4; r++) {
                float bv = xv[r + kh][kw];
                acc[0][r] += a0 * bv;
                acc[1][r] += a1 * bv;
                acc[2][r] += a2 * bv;
                acc[3][r] += a3 * bv;
            }
        }

        __syncthreads();   // everyone done reading buf[c&1] (written two iters ago)
        if (c + 1 < CI) {
            float* dst = xs + ((c + 1) & 1) * HALO_N;
            dst[e0] = n0;
            if (has1) dst[e1] = n1;
            __syncthreads();
        }
    }

    // ---- epilogue: bias + relu, coalesced stores (8 consecutive cols per om group) ----
    int o0 = og * 16 + 4 * om;
#pragma unroll
    for (int i = 0; i < 4; i++) {
        float bz = bias[o0 + i];
#pragma unroll
        for (int r = 0; r < 4; r++) {
            float v = acc[i][r] + bz;
            out[(((size_t)b * CO + o0 + i) * HH + (y0 + r)) * WW + (x0 + g)] =
                v > 0.f ? v : 0.f;
        }
    }
}

// ================================ launch ================================
extern "C" void kernel_launch(void* const* d_in, const int* in_sizes, int n_in,
                              void* d_out, int out_size) {
    const float* x       = (const float*)d_in[0];
    const float* ctx_w   = (const float*)d_in[1];
    const float* ctx_b   = (const float*)d_in[2];
    const float* kg_w    = (const float*)d_in[3];
    const float* kg_b    = (const float*)d_in[4];
    const float* gamma   = (const float*)d_in[5];
    const float* bias    = (const float*)d_in[6];
    const float* value_w = (const float*)d_in[7];
    float* out = (float*)d_out;

    k_mean<<<BB * CI, 256>>>(x);
    k_ctx<<<1, 128>>>(ctx_w, ctx_b);
    k_gen<<<BB * CO, 192>>>(kg_w, kg_b, gamma, value_w);
    dim3 grid(64, 4, BB);   // (spatial tiles: 32 rows x 2 cols, o-groups, batch)
    k_conv<<<grid, 256>>>(x, bias, out);
}

// round 2
// speedup vs baseline: 1.2708x; 1.2708x over previous
#include <cuda_runtime.h>
#include <math.h>

#define BB   8
#define CI   64
#define CO   64
#define HH   128
#define WW   128
#define CTXC 16
#define FF   576            // CI * 9
#define HWSZ (HH*WW)

#define TILE_H 8
#define TILE_W 64
#define HALO_W (TILE_W + 2)      // 66
#define HALO_H (TILE_H + 2)      // 10
#define HALO_N (HALO_H * HALO_W) // 660
#define WPAD 18                  // wsm row stride (16 o + 2 pad), even -> 8B-aligned pairs

// ---- device scratch (no allocation allowed) ----
__device__ float g_meanx[BB * CI];
__device__ float g_ctx[BB * CTXC];
__device__ float g_weff[BB * CO * FF];   // [b][o][cin*9+kk], value_w folded in

typedef unsigned long long u64t;

__device__ __forceinline__ u64t pack2(float v) {
    u64t r; asm("mov.b64 %0, {%1, %2};" : "=l"(r) : "f"(v), "f"(v)); return r;
}
__device__ __forceinline__ void ffma2(u64t& d, u64t a, u64t b) {
    asm("fma.rn.f32x2 %0, %1, %2, %0;" : "+l"(d) : "l"(a), "l"(b));
}
__device__ __forceinline__ void unpack2(u64t v, float& lo, float& hi) {
    asm("mov.b64 {%0, %1}, %2;" : "=f"(lo), "=f"(hi) : "l"(v));
}

// ================= kernel 1: spatial mean of x -> (B, C) =================
__global__ void k_mean(const float* __restrict__ x) {
    int bc = blockIdx.x;  // 0..511
    const float4* p4 = (const float4*)(x + (size_t)bc * HWSZ);
    float s = 0.f;
    for (int i = threadIdx.x; i < HWSZ / 4; i += 256) {
        float4 v = p4[i];
        s += (v.x + v.y) + (v.z + v.w);
    }
    __shared__ float red[8];
#pragma unroll
    for (int o = 16; o; o >>= 1) s += __shfl_xor_sync(0xffffffffu, s, o);
    if ((threadIdx.x & 31) == 0) red[threadIdx.x >> 5] = s;
    __syncthreads();
    if (threadIdx.x < 8) {
        s = red[threadIdx.x];
#pragma unroll
        for (int o = 4; o; o >>= 1) s += __shfl_xor_sync(0xffu, s, o);
        if (threadIdx.x == 0) g_meanx[bc] = s * (1.f / (float)HWSZ);
    }
}

// ================= kernel 2: ctx_vec = meanx @ ctx_w^T + ctx_b =================
__global__ void k_ctx(const float* __restrict__ ctx_w, const float* __restrict__ ctx_b) {
    int t = threadIdx.x;
    if (t >= BB * CTXC) return;
    int b = t >> 4, o = t & 15;
    float s = ctx_b[o];
#pragma unroll 8
    for (int c = 0; c < CI; c++) s += ctx_w[o * CI + c] * g_meanx[b * CI + c];
    g_ctx[t] = s;   // t == b*16 + o
}

// ====== kernel 3: generate per-sample kernels, center, fold in value_w ======
__global__ void k_gen(const float* __restrict__ kg_w, const float* __restrict__ kg_b,
                      const float* __restrict__ gamma, const float* __restrict__ value_w) {
    int bo = blockIdx.x;          // 0..511
    int b = bo >> 6, o = bo & 63;
    __shared__ float ctx_s[CTXC];
    __shared__ float kern_s[FF];
    __shared__ float vw_s[CI * CI];
    __shared__ float red[6];
    int t = threadIdx.x;          // 0..191
    if (t < CTXC) ctx_s[t] = g_ctx[b * CTXC + t];
    for (int i = t; i < CI * CI; i += 192) vw_s[i] = value_w[i];
    __syncthreads();

    float part = 0.f;
#pragma unroll
    for (int i = 0; i < 3; i++) {
        int f = t + 192 * i;                       // = c*9 + kk
        const float4* wr = (const float4*)(kg_w + (size_t)(o * FF + f) * 16);
        float s = kg_b[o * FF + f];
#pragma unroll
        for (int jj = 0; jj < 4; jj++) {
            float4 w = wr[jj];
            s += ctx_s[4 * jj + 0] * w.x + ctx_s[4 * jj + 1] * w.y
               + ctx_s[4 * jj + 2] * w.z + ctx_s[4 * jj + 3] * w.w;
        }
        s = tanhf(s);
        kern_s[f] = s;
        part += s;
    }
#pragma unroll
    for (int off = 16; off; off >>= 1) part += __shfl_xor_sync(0xffffffffu, part, off);
    if ((t & 31) == 0) red[t >> 5] = part;
    __syncthreads();   // also makes kern_s visible
    float total = red[0] + red[1] + red[2] + red[3] + red[4] + red[5];
    float lam = 1.f / (1.f + __expf(-gamma[o]));
    float sub = lam * total * (1.f / (float)FF);

    // W_eff[b][o][cin][kk] = sum_cp (kern[cp][kk] - sub) * value_w[cp][cin]
#pragma unroll
    for (int i = 0; i < 3; i++) {
        int f = t + 192 * i;
        int cin = f / 9, kk = f % 9;
        float s = 0.f;
#pragma unroll 16
        for (int cp = 0; cp < CI; cp++)
            s += (kern_s[cp * 9 + kk] - sub) * vw_s[cp * CI + cin];
        g_weff[(size_t)bo * FF + f] = s;
    }
}

// ================= kernel 4: dynamic 3x3 conv, f32x2 packed FMA =================
// block: 16 output channels x (8 x 64) spatial tile; 256 threads;
// per thread: 4 o (2 f32x2 pairs) x 8 rows at fixed column g.
__global__ void __launch_bounds__(256, 2)
k_conv(const float* __restrict__ x, const float* __restrict__ bias,
       float* __restrict__ out) {
    __shared__ __align__(16) float wsm[FF * WPAD];   // [f][ol] -> o-pairs adjacent
    __shared__ __align__(16) float xs[2 * HALO_N];   // double-buffered halo

    int t = threadIdx.x;
    int b  = blockIdx.z;          // 0..7
    int og = blockIdx.y;          // 0..3  -> o0 = og*16
    int ty = blockIdx.x >> 1;     // 0..15
    int tx = blockIdx.x & 1;      // 0..1
    int y0 = ty * TILE_H;
    int x0 = tx * TILE_W;
    int om = t & 3;               // o sub-group (4 o's each)
    int g  = t >> 2;              // column within tile, 0..63

    // ---- stage W_eff slice (16 o x 576 f), transposed into wsm[f*WPAD + ol] ----
    const float4* wg = (const float4*)(g_weff + (size_t)(b * CO + og * 16) * FF);
    for (int v = t; v < 16 * 144; v += 256) {
        int ol = v / 144;
        int f4 = v % 144;
        float4 w4 = wg[(size_t)ol * 144 + f4];
        int f = 4 * f4;
        wsm[(f + 0) * WPAD + ol] = w4.x;
        wsm[(f + 1) * WPAD + ol] = w4.y;
        wsm[(f + 2) * WPAD + ol] = w4.z;
        wsm[(f + 3) * WPAD + ol] = w4.w;
    }

    // ---- halo loader setup: elements t, t+256, t+512 ----
    int e0 = t;
    int hr0 = e0 / HALO_W, hc0 = e0 % HALO_W;
    int gy0 = y0 - 1 + hr0, gx0 = x0 - 1 + hc0;
    bool v0 = (gy0 >= 0) && (gy0 < HH) && (gx0 >= 0) && (gx0 < WW);
    long off0 = ((long)(b * CI) * HH + gy0) * WW + gx0;

    int e1 = t + 256;
    int hr1 = e1 / HALO_W, hc1 = e1 % HALO_W;
    int gy1 = y0 - 1 + hr1, gx1 = x0 - 1 + hc1;
    bool v1 = (gy1 >= 0) && (gy1 < HH) && (gx1 >= 0) && (gx1 < WW);
    long off1 = ((long)(b * CI) * HH + gy1) * WW + gx1;

    int e2 = t + 512;
    bool has2 = (e2 < HALO_N);
    int hr2 = e2 / HALO_W, hc2 = e2 % HALO_W;
    int gy2 = y0 - 1 + hr2, gx2 = x0 - 1 + hc2;
    bool v2 = has2 && (gy2 >= 0) && (gy2 < HH) && (gx2 >= 0) && (gx2 < WW);
    long off2 = ((long)(b * CI) * HH + gy2) * WW + gx2;

    u64t acc[2][TILE_H];
#pragma unroll
    for (int p = 0; p < 2; p++)
#pragma unroll
        for (int r = 0; r < TILE_H; r++) acc[p][r] = 0ull;

    // preload channel 0 halo into buffer 0
    {
        xs[e0] = v0 ? x[off0] : 0.f;
        xs[e1] = v1 ? x[off1] : 0.f;
        if (has2) xs[e2] = v2 ? x[off2] : 0.f;
    }
    __syncthreads();   // covers wsm staging + halo buf 0

    int wb = 4 * om;   // even -> 8B-aligned LDS.64 on wsm
    for (int c = 0; c < CI; c++) {
        // prefetch next channel's halo into registers (overlaps compute)
        float n0 = 0.f, n1 = 0.f, n2 = 0.f;
        if (c + 1 < CI) {
            long coff = (long)(c + 1) * HWSZ;
            if (v0) n0 = x[off0 + coff];
            if (v1) n1 = x[off1 + coff];
            if (v2) n2 = x[off2 + coff];
        }

        const float* cb = xs + (c & 1) * HALO_N;
        const float* wrow = wsm + c * 9 * WPAD + wb;

#pragma unroll
        for (int kw = 0; kw < 3; kw++) {
            // replicated x pairs for this kernel column
            u64t vv[HALO_H];
#pragma unroll
            for (int rr = 0; rr < HALO_H; rr++)
                vv[rr] = pack2(cb[rr * HALO_W + g + kw]);

#pragma unroll
            for (int kh = 0; kh < 3; kh++) {
                const float* wp = wrow + (kh * 3 + kw) * WPAD;
                u64t wA = *(const u64t*)(wp);       // (o0, o0+1)
                u64t wB = *(const u64t*)(wp + 2);   // (o0+2, o0+3)
#pragma unroll
                for (int r = 0; r < TILE_H; r++) {
                    ffma2(acc[0][r], wA, vv[r + kh]);
                    ffma2(acc[1][r], wB, vv[r + kh]);
                }
            }
        }

        __syncthreads();   // everyone done reading buf[c&1]
        if (c + 1 < CI) {
            float* dst = xs + ((c + 1) & 1) * HALO_N;
            dst[e0] = n0;
            dst[e1] = n1;
            if (has2) dst[e2] = n2;
            __syncthreads();
        }
    }

    // ---- epilogue: bias + relu, coalesced stores ----
    int o0 = og * 16 + wb;
#pragma unroll
    for (int p = 0; p < 2; p++) {
        float b0 = bias[o0 + 2 * p];
        float b1 = bias[o0 + 2 * p + 1];
#pragma unroll
        for (int r = 0; r < TILE_H; r++) {
            float lo, hi;
            unpack2(acc[p][r], lo, hi);
            float u0 = lo + b0, u1 = hi + b1;
            size_t base = (((size_t)b * CO + o0 + 2 * p) * HH + (y0 + r)) * WW + (x0 + g);
            out[base] = u0 > 0.f ? u0 : 0.f;
            out[base + (size_t)HH * WW] = u1 > 0.f ? u1 : 0.f;
        }
    }
}

// ================================ launch ================================
extern "C" void kernel_launch(void* const* d_in, const int* in_sizes, int n_in,
                              void* d_out, int out_size) {
    const float* x       = (const float*)d_in[0];
    const float* ctx_w   = (const float*)d_in[1];
    const float* ctx_b   = (const float*)d_in[2];
    const float* kg_w    = (const float*)d_in[3];
    const float* kg_b    = (const float*)d_in[4];
    const float* gamma   = (const float*)d_in[5];
    const float* bias    = (const float*)d_in[6];
    const float* value_w = (const float*)d_in[7];
    float* out = (float*)d_out;

    k_mean<<<BB * CI, 256>>>(x);
    k_ctx<<<1, 128>>>(ctx_w, ctx_b);
    k_gen<<<BB * CO, 192>>>(kg_w, kg_b, gamma, value_w);
    dim3 grid(32, 4, BB);   // (16 row-tiles x 2 col-tiles, o-groups, batch)
    k_conv<<<grid, 256>>>(x, bias, out);
}

// round 3
// speedup vs baseline: 1.3105x; 1.0312x over previous
#include <cuda_runtime.h>
#include <math.h>

#define BB   8
#define CI   64
#define CO   64
#define HH   128
#define WW   128
#define CTXC 16
#define FF   576            // CI * 9
#define HWSZ (HH*WW)

#define TILE_H 8
#define TILE_W 64
#define HALO_W (TILE_W + 2)      // 66
#define HALO_H (TILE_H + 2)      // 10
#define HALO_N (HALO_H * HALO_W) // 660
#define WPAD 18                  // wsm row stride (16 o + 2 pad), even -> 8B-aligned pairs

// ---- device scratch (no allocation allowed) ----
__device__ float g_meanx[BB * CI];
__device__ float g_ctx[BB * CTXC];
__device__ float g_weff[BB * CO * FF];   // [b][o][cin*9+kk], value_w folded in

typedef unsigned long long u64t;

__device__ __forceinline__ u64t pack2(float v) {
    u64t r; asm("mov.b64 %0, {%1, %2};" : "=l"(r) : "f"(v), "f"(v)); return r;
}
__device__ __forceinline__ void ffma2(u64t& d, u64t a, u64t b) {
    asm("fma.rn.f32x2 %0, %1, %2, %0;" : "+l"(d) : "l"(a), "l"(b));
}
__device__ __forceinline__ void unpack2(u64t v, float& lo, float& hi) {
    asm("mov.b64 {%0, %1}, %2;" : "=f"(lo), "=f"(hi) : "l"(v));
}
__device__ __forceinline__ void cp_async4(unsigned dst, const float* src, bool pred) {
    int sz = pred ? 4 : 0;
    asm volatile("cp.async.ca.shared.global [%0], [%1], 4, %2;"
                 :: "r"(dst), "l"(src), "r"(sz));
}
__device__ __forceinline__ void cp_commit() {
    asm volatile("cp.async.commit_group;");
}
__device__ __forceinline__ void cp_wait0() {
    asm volatile("cp.async.wait_group 0;");
}

// ================= kernel 1: spatial mean of x -> (B, C) =================
__global__ void k_mean(const float* __restrict__ x) {
    int bc = blockIdx.x;  // 0..511
    const float4* p4 = (const float4*)(x + (size_t)bc * HWSZ);
    float s = 0.f;
    for (int i = threadIdx.x; i < HWSZ / 4; i += 256) {
        float4 v = p4[i];
        s += (v.x + v.y) + (v.z + v.w);
    }
    __shared__ float red[8];
#pragma unroll
    for (int o = 16; o; o >>= 1) s += __shfl_xor_sync(0xffffffffu, s, o);
    if ((threadIdx.x & 31) == 0) red[threadIdx.x >> 5] = s;
    __syncthreads();
    if (threadIdx.x < 8) {
        s = red[threadIdx.x];
#pragma unroll
        for (int o = 4; o; o >>= 1) s += __shfl_xor_sync(0xffu, s, o);
        if (threadIdx.x == 0) g_meanx[bc] = s * (1.f / (float)HWSZ);
    }
}

// ================= kernel 2: ctx_vec = meanx @ ctx_w^T + ctx_b =================
__global__ void k_ctx(const float* __restrict__ ctx_w, const float* __restrict__ ctx_b) {
    int t = threadIdx.x;
    if (t >= BB * CTXC) return;
    int b = t >> 4, o = t & 15;
    float s = ctx_b[o];
#pragma unroll 8
    for (int c = 0; c < CI; c++) s += ctx_w[o * CI + c] * g_meanx[b * CI + c];
    g_ctx[t] = s;   // t == b*16 + o
}

// ====== kernel 3: generate per-sample kernels, center, fold in value_w ======
__global__ void k_gen(const float* __restrict__ kg_w, const float* __restrict__ kg_b,
                      const float* __restrict__ gamma, const float* __restrict__ value_w) {
    int bo = blockIdx.x;          // 0..511
    int b = bo >> 6, o = bo & 63;
    __shared__ float ctx_s[CTXC];
    __shared__ float kern_s[FF];
    __shared__ float vw_s[CI * CI];
    __shared__ float red[6];
    int t = threadIdx.x;          // 0..191
    if (t < CTXC) ctx_s[t] = g_ctx[b * CTXC + t];
    for (int i = t; i < CI * CI; i += 192) vw_s[i] = value_w[i];
    __syncthreads();

    float part = 0.f;
#pragma unroll
    for (int i = 0; i < 3; i++) {
        int f = t + 192 * i;                       // = c*9 + kk
        const float4* wr = (const float4*)(kg_w + (size_t)(o * FF + f) * 16);
        float s = kg_b[o * FF + f];
#pragma unroll
        for (int jj = 0; jj < 4; jj++) {
            float4 w = wr[jj];
            s += ctx_s[4 * jj + 0] * w.x + ctx_s[4 * jj + 1] * w.y
               + ctx_s[4 * jj + 2] * w.z + ctx_s[4 * jj + 3] * w.w;
        }
        s = tanhf(s);
        kern_s[f] = s;
        part += s;
    }
#pragma unroll
    for (int off = 16; off; off >>= 1) part += __shfl_xor_sync(0xffffffffu, part, off);
    if ((t & 31) == 0) red[t >> 5] = part;
    __syncthreads();   // also makes kern_s visible
    float total = red[0] + red[1] + red[2] + red[3] + red[4] + red[5];
    float lam = 1.f / (1.f + __expf(-gamma[o]));
    float sub = lam * total * (1.f / (float)FF);

    // W_eff[b][o][cin][kk] = sum_cp (kern[cp][kk] - sub) * value_w[cp][cin]
#pragma unroll
    for (int i = 0; i < 3; i++) {
        int f = t + 192 * i;
        int cin = f / 9, kk = f % 9;
        float s = 0.f;
#pragma unroll 16
        for (int cp = 0; cp < CI; cp++)
            s += (kern_s[cp * 9 + kk] - sub) * vw_s[cp * CI + cin];
        g_weff[(size_t)bo * FF + f] = s;
    }
}

// ================= kernel 4: dynamic 3x3 conv, f32x2 packed FMA =================
// block: 16 output channels x (8 x 64) spatial tile; 256 threads;
// per thread: 4 o (2 f32x2 pairs) x 8 rows at fixed column g.
// cp.async double-buffered halo, one barrier per channel, 3 CTAs/SM.
__global__ void __launch_bounds__(256, 3)
k_conv(const float* __restrict__ x, const float* __restrict__ bias,
       float* __restrict__ out) {
    __shared__ __align__(16) float wsm[FF * WPAD];   // [f][ol] -> o-pairs adjacent
    __shared__ __align__(16) float xs[2 * HALO_N];   // double-buffered halo

    int t = threadIdx.x;
    int b  = blockIdx.z;          // 0..7
    int og = blockIdx.y;          // 0..3  -> o0 = og*16
    int ty = blockIdx.x >> 1;     // 0..15
    int tx = blockIdx.x & 1;      // 0..1
    int y0 = ty * TILE_H;
    int x0 = tx * TILE_W;
    int om = t & 3;               // o sub-group (4 o's each)
    int g  = t >> 2;              // column within tile, 0..63

    // ---- halo loader setup: elements t, t+256, t+512 ----
    int e0 = t;
    int hr0 = e0 / HALO_W, hc0 = e0 % HALO_W;
    int gy0 = y0 - 1 + hr0, gx0 = x0 - 1 + hc0;
    bool v0 = (gy0 >= 0) && (gy0 < HH) && (gx0 >= 0) && (gx0 < WW);
    const float* p0 = x + ((long)(b * CI) * HH + (v0 ? gy0 : 0)) * WW + (v0 ? gx0 : 0);

    int e1 = t + 256;
    int hr1 = e1 / HALO_W, hc1 = e1 % HALO_W;
    int gy1 = y0 - 1 + hr1, gx1 = x0 - 1 + hc1;
    bool v1 = (gy1 >= 0) && (gy1 < HH) && (gx1 >= 0) && (gx1 < WW);
    const float* p1 = x + ((long)(b * CI) * HH + (v1 ? gy1 : 0)) * WW + (v1 ? gx1 : 0);

    int e2 = t + 512;
    bool has2 = (e2 < HALO_N);
    int hr2 = has2 ? e2 / HALO_W : 0, hc2 = has2 ? e2 % HALO_W : 0;
    int gy2 = y0 - 1 + hr2, gx2 = x0 - 1 + hc2;
    bool v2 = has2 && (gy2 >= 0) && (gy2 < HH) && (gx2 >= 0) && (gx2 < WW);
    const float* p2 = x + ((long)(b * CI) * HH + (v2 ? gy2 : 0)) * WW + (v2 ? gx2 : 0);

    unsigned sA0 = (unsigned)__cvta_generic_to_shared(xs + e0);
    unsigned sA1 = (unsigned)__cvta_generic_to_shared(xs + e1);
    unsigned sA2 = (unsigned)__cvta_generic_to_shared(xs + e2);
    unsigned sB0 = sA0 + HALO_N * 4u;
    unsigned sB1 = sA1 + HALO_N * 4u;
    unsigned sB2 = sA2 + HALO_N * 4u;

    // kick off channel-0 halo into buffer A
    cp_async4(sA0, p0, v0);
    cp_async4(sA1, p1, v1);
    if (has2) cp_async4(sA2, p2, v2);
    cp_commit();

    // ---- stage W_eff slice (16 o x 576 f), transposed into wsm[f*WPAD + ol] ----
    const float4* wg = (const float4*)(g_weff + (size_t)(b * CO + og * 16) * FF);
    for (int v = t; v < 16 * 144; v += 256) {
        int ol = v / 144;
        int f4 = v % 144;
        float4 w4 = wg[(size_t)ol * 144 + f4];
        int f = 4 * f4;
        wsm[(f + 0) * WPAD + ol] = w4.x;
        wsm[(f + 1) * WPAD + ol] = w4.y;
        wsm[(f + 2) * WPAD + ol] = w4.z;
        wsm[(f + 3) * WPAD + ol] = w4.w;
    }

    u64t acc[2][TILE_H];
#pragma unroll
    for (int p = 0; p < 2; p++)
#pragma unroll
        for (int r = 0; r < TILE_H; r++) acc[p][r] = 0ull;

    cp_wait0();
    __syncthreads();   // wsm staged + halo buf A ready

    int wb = 4 * om;   // even -> 8B-aligned LDS.64 on wsm
    for (int c = 0; c < CI; c++) {
        // async prefetch of next channel into the other buffer.
        // Safe with ONE barrier/iter: that buffer's last readers (iter c-1)
        // all passed the barrier at the end of iter c-1.
        if (c + 1 < CI) {
            long coff = (long)(c + 1) * HWSZ;
            unsigned d0, d1, d2;
            if ((c + 1) & 1) { d0 = sB0; d1 = sB1; d2 = sB2; }
            else             { d0 = sA0; d1 = sA1; d2 = sA2; }
            cp_async4(d0, p0 + coff, v0);
            cp_async4(d1, p1 + coff, v1);
            if (has2) cp_async4(d2, p2 + coff, v2);
        }
        cp_commit();

        const float* cb = xs + (c & 1) * HALO_N;
        const float* wrow = wsm + c * 9 * WPAD + wb;

#pragma unroll
        for (int kw = 0; kw < 3; kw++) {
            // replicated x pairs for this kernel column
            u64t vv[HALO_H];
#pragma unroll
            for (int rr = 0; rr < HALO_H; rr++)
                vv[rr] = pack2(cb[rr * HALO_W + g + kw]);

#pragma unroll
            for (int kh = 0; kh < 3; kh++) {
                const float* wp = wrow + (kh * 3 + kw) * WPAD;
                u64t wA = *(const u64t*)(wp);       // (o0, o0+1)
                u64t wB = *(const u64t*)(wp + 2);   // (o0+2, o0+3)
#pragma unroll
                for (int r = 0; r < TILE_H; r++) {
                    ffma2(acc[0][r], wA, vv[r + kh]);
                    ffma2(acc[1][r], wB, vv[r + kh]);
                }
            }
        }

        cp_wait0();
        __syncthreads();
    }

    // ---- epilogue: bias + relu, coalesced stores ----
    int o0 = og * 16 + wb;
#pragma unroll
    for (int p = 0; p < 2; p++) {
        float b0 = bias[o0 + 2 * p];
        float b1 = bias[o0 + 2 * p + 1];
#pragma unroll
        for (int r = 0; r < TILE_H; r++) {
            float lo, hi;
            unpack2(acc[p][r], lo, hi);
            float u0 = lo + b0, u1 = hi + b1;
            size_t base = (((size_t)b * CO + o0 + 2 * p) * HH + (y0 + r)) * WW + (x0 + g);
            out[base] = u0 > 0.f ? u0 : 0.f;
            out[base + (size_t)HH * WW] = u1 > 0.f ? u1 : 0.f;
        }
    }
}

// ================================ launch ================================
extern "C" void kernel_launch(void* const* d_in, const int* in_sizes, int n_in,
                              void* d_out, int out_size) {
    const float* x       = (const float*)d_in[0];
    const float* ctx_w   = (const float*)d_in[1];
    const float* ctx_b   = (const float*)d_in[2];
    const float* kg_w    = (const float*)d_in[3];
    const float* kg_b    = (const float*)d_in[4];
    const float* gamma   = (const float*)d_in[5];
    const float* bias    = (const float*)d_in[6];
    const float* value_w = (const float*)d_in[7];
    float* out = (float*)d_out;

    k_mean<<<BB * CI, 256>>>(x);
    k_ctx<<<1, 128>>>(ctx_w, ctx_b);
    k_gen<<<BB * CO, 192>>>(kg_w, kg_b, gamma, value_w);
    dim3 grid(32, 4, BB);   // (16 row-tiles x 2 col-tiles, o-groups, batch)
    k_conv<<<grid, 256>>>(x, bias, out);
}

// round 5
// speedup vs baseline: 1.4531x; 1.1088x over previous
#include <cuda_runtime.h>
#include <math.h>

#define BB   8
#define CI   64
#define CO   64
#define HH   128
#define WW   128
#define CTXC 16
#define FF   576            // CI * 9
#define HWSZ (HH*WW)

#define TILE_H 8
#define TILE_W 64
#define HALO_W (TILE_W + 2)      // 66
#define HALO_H (TILE_H + 2)      // 10
#define HALO_N (HALO_H * HALO_W) // 660
#define WPAD 18                  // wsm row stride (16 o + 2 pad), even -> 8B-aligned pairs
#define NT   128                 // threads per conv block

// ---- device scratch (no allocation allowed) ----
__device__ float g_meanx[BB * CI];
__device__ float g_ctx[BB * CTXC];
__device__ float g_weff[BB * CO * FF];   // [b][o][cin*9+kk], value_w folded in

typedef unsigned long long u64t;

__device__ __forceinline__ u64t pack2(float v) {
    u64t r; asm("mov.b64 %0, {%1, %2};" : "=l"(r) : "f"(v), "f"(v)); return r;
}
__device__ __forceinline__ void ffma2(u64t& d, u64t a, u64t b) {
    asm("fma.rn.f32x2 %0, %1, %2, %0;" : "+l"(d) : "l"(a), "l"(b));
}
__device__ __forceinline__ void unpack2(u64t v, float& lo, float& hi) {
    asm("mov.b64 {%0, %1}, %2;" : "=f"(lo), "=f"(hi) : "l"(v));
}
// cp-size 4; src-size = pred?4:0. src-size 0 ZERO-FILLS dst (used for image padding),
// so dst must always be a slot we own.
__device__ __forceinline__ void cp_async4(unsigned dst, const float* src, bool pred) {
    int sz = pred ? 4 : 0;
    asm volatile("cp.async.ca.shared.global [%0], [%1], 4, %2;"
                 :: "r"(dst), "l"(src), "r"(sz));
}
__device__ __forceinline__ void cp_commit() {
    asm volatile("cp.async.commit_group;");
}
__device__ __forceinline__ void cp_wait0() {
    asm volatile("cp.async.wait_group 0;");
}

// ================= kernel 1: spatial mean of x -> (B, C) =================
__global__ void k_mean(const float* __restrict__ x) {
    int bc = blockIdx.x;  // 0..511
    const float4* p4 = (const float4*)(x + (size_t)bc * HWSZ);
    float s = 0.f;
    for (int i = threadIdx.x; i < HWSZ / 4; i += 256) {
        float4 v = p4[i];
        s += (v.x + v.y) + (v.z + v.w);
    }
    __shared__ float red[8];
#pragma unroll
    for (int o = 16; o; o >>= 1) s += __shfl_xor_sync(0xffffffffu, s, o);
    if ((threadIdx.x & 31) == 0) red[threadIdx.x >> 5] = s;
    __syncthreads();
    if (threadIdx.x < 8) {
        s = red[threadIdx.x];
#pragma unroll
        for (int o = 4; o; o >>= 1) s += __shfl_xor_sync(0xffu, s, o);
        if (threadIdx.x == 0) g_meanx[bc] = s * (1.f / (float)HWSZ);
    }
}

// ================= kernel 2: ctx_vec = meanx @ ctx_w^T + ctx_b =================
__global__ void k_ctx(const float* __restrict__ ctx_w, const float* __restrict__ ctx_b) {
    int t = threadIdx.x;
    if (t >= BB * CTXC) return;
    int b = t >> 4, o = t & 15;
    float s = ctx_b[o];
#pragma unroll 8
    for (int c = 0; c < CI; c++) s += ctx_w[o * CI + c] * g_meanx[b * CI + c];
    g_ctx[t] = s;   // t == b*16 + o
}

// ====== kernel 3: generate per-sample kernels, center, fold in value_w ======
__global__ void k_gen(const float* __restrict__ kg_w, const float* __restrict__ kg_b,
                      const float* __restrict__ gamma, const float* __restrict__ value_w) {
    int bo = blockIdx.x;          // 0..511
    int b = bo >> 6, o = bo & 63;
    __shared__ float ctx_s[CTXC];
    __shared__ float kern_s[FF];
    __shared__ float vw_s[CI * CI];
    __shared__ float red[6];
    int t = threadIdx.x;          // 0..191
    if (t < CTXC) ctx_s[t] = g_ctx[b * CTXC + t];
    for (int i = t; i < CI * CI; i += 192) vw_s[i] = value_w[i];
    __syncthreads();

    float part = 0.f;
#pragma unroll
    for (int i = 0; i < 3; i++) {
        int f = t + 192 * i;                       // = c*9 + kk
        const float4* wr = (const float4*)(kg_w + (size_t)(o * FF + f) * 16);
        float s = kg_b[o * FF + f];
#pragma unroll
        for (int jj = 0; jj < 4; jj++) {
            float4 w = wr[jj];
            s += ctx_s[4 * jj + 0] * w.x + ctx_s[4 * jj + 1] * w.y
               + ctx_s[4 * jj + 2] * w.z + ctx_s[4 * jj + 3] * w.w;
        }
        s = tanhf(s);
        kern_s[f] = s;
        part += s;
    }
#pragma unroll
    for (int off = 16; off; off >>= 1) part += __shfl_xor_sync(0xffffffffu, part, off);
    if ((t & 31) == 0) red[t >> 5] = part;
    __syncthreads();   // also makes kern_s visible
    float total = red[0] + red[1] + red[2] + red[3] + red[4] + red[5];
    float lam = 1.f / (1.f + __expf(-gamma[o]));
    float sub = lam * total * (1.f / (float)FF);

    // W_eff[b][o][cin][kk] = sum_cp (kern[cp][kk] - sub) * value_w[cp][cin]
#pragma unroll
    for (int i = 0; i < 3; i++) {
        int f = t + 192 * i;
        int cin = f / 9, kk = f % 9;
        float s = 0.f;
#pragma unroll 16
        for (int cp = 0; cp < CI; cp++)
            s += (kern_s[cp * 9 + kk] - sub) * vw_s[cp * CI + cin];
        g_weff[(size_t)bo * FF + f] = s;
    }
}

// ============ kernel 4: dynamic 3x3 conv, f32x2, 8 o per thread ============
// block: 16 output channels x (8 x 64) spatial tile; 128 threads;
// thread (om, g): om = t&1 -> o in [8*om, 8*om+8), column g = t>>1.
// per thread: 4 f32x2 o-pairs x 8 rows = 32 accumulators.
__global__ void __launch_bounds__(NT, 4)
k_conv(const float* __restrict__ x, const float* __restrict__ bias,
       float* __restrict__ out) {
    __shared__ __align__(16) float wsm[FF * WPAD];   // [f][ol] -> o-pairs adjacent
    __shared__ __align__(16) float xs[2 * HALO_N];   // double-buffered halo

    int t = threadIdx.x;
    int b  = blockIdx.z;          // 0..7
    int og = blockIdx.y;          // 0..3  -> o0 = og*16
    int ty = blockIdx.x >> 1;     // 0..15
    int tx = blockIdx.x & 1;      // 0..1
    int y0 = ty * TILE_H;
    int x0 = tx * TILE_W;
    int om = t & 1;               // o half (8 o's each)
    int g  = t >> 1;              // column within tile, 0..63

    // ---- halo loader: elements t + 128*i, i=0..4 always valid; i=5 guarded ----
    const float* ps[6];
    bool vs[6];
    unsigned sA[6];
    long cbase = (long)(b * CI) * HH;
    bool in5 = (t + NT * 5 < HALO_N);   // only thread t<20 owns a 6th element
#pragma unroll
    for (int i = 0; i < 6; i++) {
        int e = t + NT * i;
        int ec = (i == 5 && !in5) ? 0 : e;   // clamp for address calc only
        int hr = ec / HALO_W, hc = ec % HALO_W;
        int gy = y0 - 1 + hr, gx = x0 - 1 + hc;
        bool v = (gy >= 0) && (gy < HH) && (gx >= 0) && (gx < WW);
        ps[i] = x + (cbase + (v ? gy : 0)) * WW + (v ? gx : 0);
        vs[i] = v;
        sA[i] = (unsigned)__cvta_generic_to_shared(xs + ec);
    }

    // kick off channel-0 halo into buffer A
#pragma unroll
    for (int i = 0; i < 5; i++) cp_async4(sA[i], ps[i], vs[i]);
    if (in5) cp_async4(sA[5], ps[5], vs[5]);
    cp_commit();

    // ---- stage W_eff slice (16 o x 576 f), transposed into wsm[f*WPAD + ol] ----
    const float4* wg = (const float4*)(g_weff + (size_t)(b * CO + og * 16) * FF);
    for (int v = t; v < 16 * 144; v += NT) {
        int ol = v / 144;
        int f4 = v % 144;
        float4 w4 = wg[(size_t)ol * 144 + f4];
        int f = 4 * f4;
        wsm[(f + 0) * WPAD + ol] = w4.x;
        wsm[(f + 1) * WPAD + ol] = w4.y;
        wsm[(f + 2) * WPAD + ol] = w4.z;
        wsm[(f + 3) * WPAD + ol] = w4.w;
    }

    u64t acc[4][TILE_H];
#pragma unroll
    for (int p = 0; p < 4; p++)
#pragma unroll
        for (int r = 0; r < TILE_H; r++) acc[p][r] = 0ull;

    cp_wait0();
    __syncthreads();   // wsm staged + halo buf A ready

    int wb = 8 * om;   // even -> 8B-aligned LDS.64 on wsm
    for (int c = 0; c < CI; c++) {
        // async prefetch of next channel into the other buffer.
        // ONE barrier/iter is safe: that buffer's last readers (iter c-1)
        // all passed the barrier at the end of iter c-1.
        if (c + 1 < CI) {
            long coff = (long)(c + 1) * HWSZ;
            unsigned boff = ((c + 1) & 1) ? HALO_N * 4u : 0u;
#pragma unroll
            for (int i = 0; i < 5; i++)
                cp_async4(sA[i] + boff, ps[i] + coff, vs[i]);
            if (in5) cp_async4(sA[5] + boff, ps[5] + coff, vs[5]);
        }
        cp_commit();

        const float* cb = xs + (c & 1) * HALO_N;
        const float* wrow = wsm + c * 9 * WPAD + wb;

#pragma unroll
        for (int kw = 0; kw < 3; kw++) {
            // replicated x pairs for this kernel column
            u64t vv[HALO_H];
#pragma unroll
            for (int rr = 0; rr < HALO_H; rr++)
                vv[rr] = pack2(cb[rr * HALO_W + g + kw]);

#pragma unroll
            for (int kh = 0; kh < 3; kh++) {
                const float* wp = wrow + (kh * 3 + kw) * WPAD;
                u64t w0 = *(const u64t*)(wp);       // (o, o+1)
                u64t w1 = *(const u64t*)(wp + 2);
                u64t w2 = *(const u64t*)(wp + 4);
                u64t w3 = *(const u64t*)(wp + 6);
#pragma unroll
                for (int r = 0; r < TILE_H; r++) {
                    u64t xvv = vv[r + kh];
                    ffma2(acc[0][r], w0, xvv);
                    ffma2(acc[1][r], w1, xvv);
                    ffma2(acc[2][r], w2, xvv);
                    ffma2(acc[3][r], w3, xvv);
                }
            }
        }

        cp_wait0();
        __syncthreads();
    }

    // ---- epilogue: bias + relu ----
    int o0 = og * 16 + wb;
#pragma unroll
    for (int p = 0; p < 4; p++) {
        float b0 = bias[o0 + 2 * p];
        float b1 = bias[o0 + 2 * p + 1];
#pragma unroll
        for (int r = 0; r < TILE_H; r++) {
            float lo, hi;
            unpack2(acc[p][r], lo, hi);
            float u0 = lo + b0, u1 = hi + b1;
            size_t base = (((size_t)b * CO + o0 + 2 * p) * HH + (y0 + r)) * WW + (x0 + g);
            out[base] = u0 > 0.f ? u0 : 0.f;
            out[base + (size_t)HH * WW] = u1 > 0.f ? u1 : 0.f;
        }
    }
}

// ================================ launch ================================
extern "C" void kernel_launch(void* const* d_in, const int* in_sizes, int n_in,
                              void* d_out, int out_size) {
    const float* x       = (const float*)d_in[0];
    const float* ctx_w   = (const float*)d_in[1];
    const float* ctx_b   = (const float*)d_in[2];
    const float* kg_w    = (const float*)d_in[3];
    const float* kg_b    = (const float*)d_in[4];
    const float* gamma   = (const float*)d_in[5];
    const float* bias    = (const float*)d_in[6];
    const float* value_w = (const float*)d_in[7];
    float* out = (float*)d_out;

    k_mean<<<BB * CI, 256>>>(x);
    k_ctx<<<1, 128>>>(ctx_w, ctx_b);
    k_gen<<<BB * CO, 192>>>(kg_w, kg_b, gamma, value_w);
    dim3 grid(32, 4, BB);   // (16 row-tiles x 2 col-tiles, o-groups, batch)
    k_conv<<<grid, NT>>>(x, bias, out);
}

// round 6
// speedup vs baseline: 1.4811x; 1.0193x over previous
#include <cuda_runtime.h>
#include <math.h>

#define BB   8
#define CI   64
#define CO   64
#define HH   128
#define WW   128
#define CTXC 16
#define FF   576            // CI * 9
#define HWSZ (HH*WW)

#define TILE_H 8
#define TILE_W 64
#define HALO_W (TILE_W + 2)      // 66
#define HALO_H (TILE_H + 2)      // 10
#define HALO_N (HALO_H * HALO_W) // 660
#define WPAD 18                  // wsm row stride (16 o + 2 pad), even -> 8B-aligned pairs
#define NT   128                 // threads per conv block
#define NSTG 32                  // channel stages (2 channels each)

// ---- device scratch (no allocation allowed) ----
__device__ float g_meanx[BB * CI];
__device__ float g_weff[BB * CO * FF];   // [b][o][cin*9+kk], value_w folded in

typedef unsigned long long u64t;

__device__ __forceinline__ u64t pack2(float v) {
    u64t r; asm("mov.b64 %0, {%1, %2};" : "=l"(r) : "f"(v), "f"(v)); return r;
}
__device__ __forceinline__ void ffma2(u64t& d, u64t a, u64t b) {
    asm("fma.rn.f32x2 %0, %1, %2, %0;" : "+l"(d) : "l"(a), "l"(b));
}
__device__ __forceinline__ void unpack2(u64t v, float& lo, float& hi) {
    asm("mov.b64 {%0, %1}, %2;" : "=f"(lo), "=f"(hi) : "l"(v));
}
// cp-size 4; src-size = pred?4:0. src-size 0 ZERO-FILLS dst (used for image padding),
// so dst must always be a slot we own.
__device__ __forceinline__ void cp_async4(unsigned dst, const float* src, bool pred) {
    int sz = pred ? 4 : 0;
    asm volatile("cp.async.ca.shared.global [%0], [%1], 4, %2;"
                 :: "r"(dst), "l"(src), "r"(sz));
}
__device__ __forceinline__ void cp_commit() {
    asm volatile("cp.async.commit_group;");
}
__device__ __forceinline__ void cp_wait0() {
    asm volatile("cp.async.wait_group 0;");
}

// ================= kernel 1: spatial mean of x -> (B, C) =================
__global__ void k_mean(const float* __restrict__ x) {
    int bc = blockIdx.x;  // 0..511
    const float4* p4 = (const float4*)(x + (size_t)bc * HWSZ);
    float s = 0.f;
    for (int i = threadIdx.x; i < HWSZ / 4; i += 256) {
        float4 v = p4[i];
        s += (v.x + v.y) + (v.z + v.w);
    }
    __shared__ float red[8];
#pragma unroll
    for (int o = 16; o; o >>= 1) s += __shfl_xor_sync(0xffffffffu, s, o);
    if ((threadIdx.x & 31) == 0) red[threadIdx.x >> 5] = s;
    __syncthreads();
    if (threadIdx.x < 8) {
        s = red[threadIdx.x];
#pragma unroll
        for (int o = 4; o; o >>= 1) s += __shfl_xor_sync(0xffu, s, o);
        if (threadIdx.x == 0) g_meanx[bc] = s * (1.f / (float)HWSZ);
    }
}

// == kernel 2: generate per-sample kernels, center, fold in value_w (ctx fused) ==
__global__ void k_gen(const float* __restrict__ ctx_w, const float* __restrict__ ctx_b,
                      const float* __restrict__ kg_w, const float* __restrict__ kg_b,
                      const float* __restrict__ gamma, const float* __restrict__ value_w) {
    int bo = blockIdx.x;          // 0..511
    int b = bo >> 6, o = bo & 63;
    __shared__ float ctx_s[CTXC];
    __shared__ float kern_s[FF];
    __shared__ float vw_s[CI * CI];
    __shared__ float red[6];
    int t = threadIdx.x;          // 0..191
    if (t < CTXC) {
        float s = ctx_b[t];
#pragma unroll 8
        for (int c = 0; c < CI; c++) s += ctx_w[t * CI + c] * g_meanx[b * CI + c];
        ctx_s[t] = s;
    }
    for (int i = t; i < CI * CI; i += 192) vw_s[i] = value_w[i];
    __syncthreads();

    float part = 0.f;
#pragma unroll
    for (int i = 0; i < 3; i++) {
        int f = t + 192 * i;                       // = c*9 + kk
        const float4* wr = (const float4*)(kg_w + (size_t)(o * FF + f) * 16);
        float s = kg_b[o * FF + f];
#pragma unroll
        for (int jj = 0; jj < 4; jj++) {
            float4 w = wr[jj];
            s += ctx_s[4 * jj + 0] * w.x + ctx_s[4 * jj + 1] * w.y
               + ctx_s[4 * jj + 2] * w.z + ctx_s[4 * jj + 3] * w.w;
        }
        s = tanhf(s);
        kern_s[f] = s;
        part += s;
    }
#pragma unroll
    for (int off = 16; off; off >>= 1) part += __shfl_xor_sync(0xffffffffu, part, off);
    if ((t & 31) == 0) red[t >> 5] = part;
    __syncthreads();   // also makes kern_s visible
    float total = red[0] + red[1] + red[2] + red[3] + red[4] + red[5];
    float lam = 1.f / (1.f + __expf(-gamma[o]));
    float sub = lam * total * (1.f / (float)FF);

    // W_eff[b][o][cin][kk] = sum_cp (kern[cp][kk] - sub) * value_w[cp][cin]
#pragma unroll
    for (int i = 0; i < 3; i++) {
        int f = t + 192 * i;
        int cin = f / 9, kk = f % 9;
        float s = 0.f;
#pragma unroll 16
        for (int cp = 0; cp < CI; cp++)
            s += (kern_s[cp * 9 + kk] - sub) * vw_s[cp * CI + cin];
        g_weff[(size_t)bo * FF + f] = s;
    }
}

// ============ kernel 3: dynamic 3x3 conv, f32x2, 8 o per thread ============
// block: 16 output channels x (8 x 64) spatial tile; 128 threads;
// thread (om, g): om = t&1 -> o in [8*om, 8*om+8), column g = t>>1.
// per thread: 4 f32x2 o-pairs x 8 rows = 32 accumulators.
// 2-channel smem stages, double-buffered: 32 barriers total.
__global__ void __launch_bounds__(NT, 4)
k_conv(const float* __restrict__ x, const float* __restrict__ bias,
       float* __restrict__ out) {
    __shared__ __align__(16) float wsm[FF * WPAD];       // [f][ol] -> o-pairs adjacent
    __shared__ __align__(16) float xs[4 * HALO_N];       // 2 stages x 2 channels

    int t = threadIdx.x;
    int b  = blockIdx.z;          // 0..7
    int og = blockIdx.y;          // 0..3  -> o0 = og*16
    int ty = blockIdx.x >> 1;     // 0..15
    int tx = blockIdx.x & 1;      // 0..1
    int y0 = ty * TILE_H;
    int x0 = tx * TILE_W;
    int om = t & 1;               // o half (8 o's each)
    int g  = t >> 1;              // column within tile, 0..63

    // ---- halo loader: elements t + 128*i, i=0..4 always valid; i=5 guarded ----
    const float* ps[6];
    bool vs[6];
    unsigned sA[6];               // stage0/ch0 smem addr per slot
    long cbase = (long)(b * CI) * HH;
    bool in5 = (t + NT * 5 < HALO_N);   // only t<20 owns a 6th element
#pragma unroll
    for (int i = 0; i < 6; i++) {
        int e = t + NT * i;
        int ec = (i == 5 && !in5) ? 0 : e;   // clamp for address calc only
        int hr = ec / HALO_W, hc = ec % HALO_W;
        int gy = y0 - 1 + hr, gx = x0 - 1 + hc;
        bool v = (gy >= 0) && (gy < HH) && (gx >= 0) && (gx < WW);
        ps[i] = x + (cbase + (v ? gy : 0)) * WW + (v ? gx : 0);
        vs[i] = v;
        sA[i] = (unsigned)__cvta_generic_to_shared(xs + ec);
    }

    // kick off stage-0 halo (channels 0,1) into buffer 0
#pragma unroll
    for (int cc = 0; cc < 2; cc++) {
        long coff = (long)cc * HWSZ;
        unsigned soff = (unsigned)cc * (HALO_N * 4u);
#pragma unroll
        for (int i = 0; i < 5; i++) cp_async4(sA[i] + soff, ps[i] + coff, vs[i]);
        if (in5) cp_async4(sA[5] + soff, ps[5] + coff, vs[5]);
    }
    cp_commit();

    // ---- stage W_eff slice (16 o x 576 f), transposed into wsm[f*WPAD + ol] ----
    const float4* wg = (const float4*)(g_weff + (size_t)(b * CO + og * 16) * FF);
    for (int v = t; v < 16 * 144; v += NT) {
        int ol = v / 144;
        int f4 = v % 144;
        float4 w4 = wg[(size_t)ol * 144 + f4];
        int f = 4 * f4;
        wsm[(f + 0) * WPAD + ol] = w4.x;
        wsm[(f + 1) * WPAD + ol] = w4.y;
        wsm[(f + 2) * WPAD + ol] = w4.z;
        wsm[(f + 3) * WPAD + ol] = w4.w;
    }

    u64t acc[4][TILE_H];
#pragma unroll
    for (int p = 0; p < 4; p++)
#pragma unroll
        for (int r = 0; r < TILE_H; r++) acc[p][r] = 0ull;

    cp_wait0();
    __syncthreads();   // wsm staged + stage-0 halo ready

    int wb = 8 * om;   // even -> 8B-aligned LDS.64 on wsm
    for (int st = 0; st < NSTG; st++) {
        // async prefetch of stage st+1 (channels 2st+2, 2st+3) into other buffer.
        // ONE barrier/stage is safe: that buffer's last readers (stage st-1)
        // all passed the barrier at the end of stage st-1.
        if (st + 1 < NSTG) {
            unsigned boff = ((st + 1) & 1) ? 2u * HALO_N * 4u : 0u;
#pragma unroll
            for (int cc = 0; cc < 2; cc++) {
                long coff = (long)(2 * st + 2 + cc) * HWSZ;
                unsigned soff = boff + (unsigned)cc * (HALO_N * 4u);
#pragma unroll
                for (int i = 0; i < 5; i++) cp_async4(sA[i] + soff, ps[i] + coff, vs[i]);
                if (in5) cp_async4(sA[5] + soff, ps[5] + coff, vs[5]);
            }
        }
        cp_commit();

#pragma unroll
        for (int cc = 0; cc < 2; cc++) {
            const float* cb = xs + (st & 1) * (2 * HALO_N) + cc * HALO_N;
            const float* wrow = wsm + (2 * st + cc) * 9 * WPAD + wb;

#pragma unroll
            for (int kw = 0; kw < 3; kw++) {
                // replicated x pairs for this kernel column
                u64t vv[HALO_H];
#pragma unroll
                for (int rr = 0; rr < HALO_H; rr++)
                    vv[rr] = pack2(cb[rr * HALO_W + g + kw]);

#pragma unroll
                for (int kh = 0; kh < 3; kh++) {
                    const float* wp = wrow + (kh * 3 + kw) * WPAD;
                    u64t w0 = *(const u64t*)(wp);       // (o, o+1)
                    u64t w1 = *(const u64t*)(wp + 2);
                    u64t w2 = *(const u64t*)(wp + 4);
                    u64t w3 = *(const u64t*)(wp + 6);
#pragma unroll
                    for (int r = 0; r < TILE_H; r++) {
                        u64t xvv = vv[r + kh];
                        ffma2(acc[0][r], w0, xvv);
                        ffma2(acc[1][r], w1, xvv);
                        ffma2(acc[2][r], w2, xvv);
                        ffma2(acc[3][r], w3, xvv);
                    }
                }
            }
        }

        cp_wait0();
        __syncthreads();
    }

    // ---- epilogue: bias + relu ----
    int o0 = og * 16 + wb;
#pragma unroll
    for (int p = 0; p < 4; p++) {
        float b0 = bias[o0 + 2 * p];
        float b1 = bias[o0 + 2 * p + 1];
#pragma unroll
        for (int r = 0; r < TILE_H; r++) {
            float lo, hi;
            unpack2(acc[p][r], lo, hi);
            float u0 = lo + b0, u1 = hi + b1;
            size_t base = (((size_t)b * CO + o0 + 2 * p) * HH + (y0 + r)) * WW + (x0 + g);
            out[base] = u0 > 0.f ? u0 : 0.f;
            out[base + (size_t)HH * WW] = u1 > 0.f ? u1 : 0.f;
        }
    }
}

// ================================ launch ================================
extern "C" void kernel_launch(void* const* d_in, const int* in_sizes, int n_in,
                              void* d_out, int out_size) {
    const float* x       = (const float*)d_in[0];
    const float* ctx_w   = (const float*)d_in[1];
    const float* ctx_b   = (const float*)d_in[2];
    const float* kg_w    = (const float*)d_in[3];
    const float* kg_b    = (const float*)d_in[4];
    const float* gamma   = (const float*)d_in[5];
    const float* bias    = (const float*)d_in[6];
    const float* value_w = (const float*)d_in[7];
    float* out = (float*)d_out;

    k_mean<<<BB * CI, 256>>>(x);
    k_gen<<<BB * CO, 192>>>(ctx_w, ctx_b, kg_w, kg_b, gamma, value_w);
    dim3 grid(32, 4, BB);   // (16 row-tiles x 2 col-tiles, o-groups, batch)
    k_conv<<<grid, NT>>>(x, bias, out);
}

// round 8
// speedup vs baseline: 1.9384x; 1.3088x over previous
#include <cuda_runtime.h>
#include <math.h>
#include <cstdint>

#define BB   8
#define CI   64
#define CO   64
#define HH   128
#define WW   128
#define CTXC 16
#define FF   576
#define HWSZ (HH*WW)

// conv smem layout (floats)
#define XROW 134                    // 130 valid cols + pad (plane stride 536 % 32 = 24)
#define XCH  (16*4*XROW)            // 8576 floats per x chunk
#define WROW 72                     // 64 o + pad (72 % 32 = 8)
#define WCH  (9*16*WROW)            // 10368 floats per W chunk
#define SMF  (2*XCH + 2*WCH)        // 37888 floats = 151552 B
#define WS0  (2*XCH)                // W buffers after x buffers

// ---- device scratch ----
__device__ float g_meanx[BB * CI];
__device__ __align__(16) float g_wt[BB * 9 * CI * CO];  // [b][tap=kh*3+kw][cin][o], tf32-rounded

__device__ __forceinline__ uint32_t tf32_rna(float v) {
    uint32_t u; asm("cvt.rna.tf32.f32 %0, %1;" : "=r"(u) : "f"(v)); return u;
}
// cp-size 4; src-size = pred?4:0 (zero-fills dst when pred false -> image padding)
__device__ __forceinline__ void cp_async4(uint32_t dst, const float* src, bool pred) {
    int sz = pred ? 4 : 0;
    asm volatile("cp.async.ca.shared.global [%0], [%1], 4, %2;"
                 :: "r"(dst), "l"(src), "r"(sz));
}
__device__ __forceinline__ void cp_async16(uint32_t dst, const void* src) {
    asm volatile("cp.async.cg.shared.global [%0], [%1], 16;" :: "r"(dst), "l"(src));
}
__device__ __forceinline__ void cp_commit() { asm volatile("cp.async.commit_group;"); }

// ================= kernel 1: spatial mean of x -> (B, C) =================
__global__ void k_mean(const float* __restrict__ x) {
    int bc = blockIdx.x;
    const float4* p4 = (const float4*)(x + (size_t)bc * HWSZ);
    float s = 0.f;
    for (int i = threadIdx.x; i < HWSZ / 4; i += 256) {
        float4 v = p4[i];
        s += (v.x + v.y) + (v.z + v.w);
    }
    __shared__ float red[8];
#pragma unroll
    for (int o = 16; o; o >>= 1) s += __shfl_xor_sync(0xffffffffu, s, o);
    if ((threadIdx.x & 31) == 0) red[threadIdx.x >> 5] = s;
    __syncthreads();
    if (threadIdx.x < 8) {
        s = red[threadIdx.x];
#pragma unroll
        for (int o = 4; o; o >>= 1) s += __shfl_xor_sync(0xffu, s, o);
        if (threadIdx.x == 0) g_meanx[bc] = s * (1.f / (float)HWSZ);
    }
}

// == kernel 2: generate kernels, center, fold value_w -> g_wt (tf32-rounded) ==
__global__ void k_gen(const float* __restrict__ ctx_w, const float* __restrict__ ctx_b,
                      const float* __restrict__ kg_w, const float* __restrict__ kg_b,
                      const float* __restrict__ gamma, const float* __restrict__ value_w) {
    int bo = blockIdx.x;          // 0..511
    int b = bo >> 6, o = bo & 63;
    __shared__ float ctx_s[CTXC];
    __shared__ float kern_s[FF];
    __shared__ float vw_s[CI * CI];
    __shared__ float red[6];
    int t = threadIdx.x;          // 0..191
    if (t < CTXC) {
        float s = ctx_b[t];
#pragma unroll 8
        for (int c = 0; c < CI; c++) s += ctx_w[t * CI + c] * g_meanx[b * CI + c];
        ctx_s[t] = s;
    }
    for (int i = t; i < CI * CI; i += 192) vw_s[i] = value_w[i];
    __syncthreads();

    float part = 0.f;
#pragma unroll
    for (int i = 0; i < 3; i++) {
        int f = t + 192 * i;                       // = c*9 + kk, kk = kh*3+kw
        const float4* wr = (const float4*)(kg_w + (size_t)(o * FF + f) * 16);
        float s = kg_b[o * FF + f];
#pragma unroll
        for (int jj = 0; jj < 4; jj++) {
            float4 w = wr[jj];
            s += ctx_s[4 * jj + 0] * w.x + ctx_s[4 * jj + 1] * w.y
               + ctx_s[4 * jj + 2] * w.z + ctx_s[4 * jj + 3] * w.w;
        }
        s = tanhf(s);
        kern_s[f] = s;
        part += s;
    }
#pragma unroll
    for (int off = 16; off; off >>= 1) part += __shfl_xor_sync(0xffffffffu, part, off);
    if ((t & 31) == 0) red[t >> 5] = part;
    __syncthreads();
    float total = red[0] + red[1] + red[2] + red[3] + red[4] + red[5];
    float lam = 1.f / (1.f + __expf(-gamma[o]));
    float sub = lam * total * (1.f / (float)FF);

    // W_eff[o][cin][kk] = sum_cp (kern[cp][kk] - sub) * value_w[cp][cin]
#pragma unroll
    for (int i = 0; i < 3; i++) {
        int f = t + 192 * i;
        int cin = f / 9, kk = f % 9;    // kk = tap = kh*3 + kw
        float s = 0.f;
#pragma unroll 16
        for (int cp = 0; cp < CI; cp++)
            s += (kern_s[cp * 9 + kk] - sub) * vw_s[cp * CI + cin];
        ((uint32_t*)g_wt)[(((size_t)b * 9 + kk) * CI + cin) * CO + o] = tf32_rna(s);
    }
}

// ======== kernel 3: conv via mma.sync m16n8k8 tf32 (implicit GEMM) ========
// CTA 256 thr (8 warps): 64 o x 2 rows x 128 cols. warp = (mi = wid&3, rowi = wid>>2).
// K = 576 in 4 chunks of 16ch x 9 taps; double-buffered cp.async.
__device__ __forceinline__ void load_chunk(uint32_t sb, const float* __restrict__ x,
                                           int b, int kc, int y0, int buf, int t) {
    // x part: 16 ch x 4 rows x 130 cols (halo) with zero-fill padding
    uint32_t xd = sb + (uint32_t)(buf * XCH) * 4u;
    const float* xb = x + ((size_t)(b * CI + kc * 16)) * HWSZ;
#pragma unroll
    for (int i = 0; i < 33; i++) {
        int e = t + 256 * i;
        if (e < 16 * 4 * 130) {
            int c = e / 520;
            int rem = e - c * 520;
            int r = rem / 130;
            int j = rem - r * 130;
            int gy = y0 - 1 + r, gx = j - 1;
            bool ok = (gy >= 0) && (gy < HH) && (gx >= 0) && (gx < WW);
            const float* src = xb + (size_t)c * HWSZ + (ok ? gy : 0) * WW + (ok ? gx : 0);
            cp_async4(xd + (uint32_t)(((c * 4 + r) * XROW + j) * 4), src, ok);
        }
    }
    // W part: 9 taps x 16 c x 64 o, rows padded to 72
    uint32_t wd = sb + (uint32_t)((WS0 + buf * WCH)) * 4u;
    const float* wb = g_wt + ((size_t)b * 9) * CI * CO;
#pragma unroll
    for (int i = 0; i < 9; i++) {
        int v = t + 256 * i;           // 0..2303
        int tap = v >> 8;
        int rem = v & 255;
        int cl = rem >> 4, o4 = rem & 15;
        const void* src = wb + ((size_t)tap * CI + kc * 16 + cl) * CO + o4 * 4;
        cp_async16(wd + (uint32_t)(((tap * 16 + cl) * WROW + o4 * 4) * 4), src);
    }
}

__global__ void __launch_bounds__(256, 1)
k_conv(const float* __restrict__ x, const float* __restrict__ bias,
       float* __restrict__ out) {
    extern __shared__ __align__(16) float smem[];
    uint32_t sb = (uint32_t)__cvta_generic_to_shared(smem);
    int t = threadIdx.x;
    int lane = t & 31, wid = t >> 5;
    int mi = wid & 3, rowi = wid >> 2;
    int o_base = mi * 16;
    int l4 = lane & 3, l2 = lane >> 2;
    int b = blockIdx.y, band = blockIdx.x;
    int y0 = band * 2;
    int y = y0 + rowi;

    float acc[16][4];
#pragma unroll
    for (int n = 0; n < 16; n++)
#pragma unroll
        for (int i = 0; i < 4; i++) acc[n][i] = 0.f;

    load_chunk(sb, x, b, 0, y0, 0, t);
    cp_commit();

    for (int kc = 0; kc < 4; kc++) {
        if (kc < 3) {
            load_chunk(sb, x, b, kc + 1, y0, (kc + 1) & 1, t);
            cp_commit();
            asm volatile("cp.async.wait_group 1;");
        } else {
            asm volatile("cp.async.wait_group 0;");
        }
        __syncthreads();

        const float* xs = smem + (kc & 1) * XCH;
        const float* ws = smem + WS0 + (kc & 1) * WCH;

        for (int tap = 0; tap < 9; tap++) {
            int kh = tap / 3, kw = tap % 3;
#pragma unroll
            for (int h = 0; h < 2; h++) {
                const float* wp = ws + (tap * 16 + h * 8 + l4) * WROW + o_base + l2;
                uint32_t a0 = __float_as_uint(wp[0]);
                uint32_t a1 = __float_as_uint(wp[8]);
                uint32_t a2 = __float_as_uint(wp[4 * WROW]);
                uint32_t a3 = __float_as_uint(wp[4 * WROW + 8]);
                const float* xp = xs + ((h * 8 + l4) * 4 + rowi + kh) * XROW + l2 + kw;
                const float* xq = xp + 4 * 4 * XROW;   // +4 channel planes
#pragma unroll
                for (int nt = 0; nt < 16; nt++) {
                    uint32_t b0 = tf32_rna(xp[nt * 8]);
                    uint32_t b1 = tf32_rna(xq[nt * 8]);
                    asm volatile(
                        "mma.sync.aligned.m16n8k8.row.col.f32.tf32.tf32.f32 "
                        "{%0,%1,%2,%3}, {%4,%5,%6,%7}, {%8,%9}, {%0,%1,%2,%3};"
                        : "+f"(acc[nt][0]), "+f"(acc[nt][1]),
                          "+f"(acc[nt][2]), "+f"(acc[nt][3])
                        : "r"(a0), "r"(a1), "r"(a2), "r"(a3), "r"(b0), "r"(b1));
                }
            }
        }
        __syncthreads();
    }

    // ---- epilogue: bias + relu ----
    int o = o_base + l2;
    float bz0 = bias[o], bz1 = bias[o + 8];
    float* r0 = out + (((size_t)b * CO + o) * HH + y) * WW;
    float* r1 = r0 + (size_t)8 * HH * WW;
#pragma unroll
    for (int nt = 0; nt < 16; nt++) {
        int col = nt * 8 + l4 * 2;
        float2 v0, v1;
        float u0 = acc[nt][0] + bz0, u1 = acc[nt][1] + bz0;
        float u2 = acc[nt][2] + bz1, u3 = acc[nt][3] + bz1;
        v0.x = u0 > 0.f ? u0 : 0.f;
        v0.y = u1 > 0.f ? u1 : 0.f;
        v1.x = u2 > 0.f ? u2 : 0.f;
        v1.y = u3 > 0.f ? u3 : 0.f;
        *(float2*)(r0 + col) = v0;
        *(float2*)(r1 + col) = v1;
    }
}

// ================================ launch ================================
extern "C" void kernel_launch(void* const* d_in, const int* in_sizes, int n_in,
                              void* d_out, int out_size) {
    const float* x       = (const float*)d_in[0];
    const float* ctx_w   = (const float*)d_in[1];
    const float* ctx_b   = (const float*)d_in[2];
    const float* kg_w    = (const float*)d_in[3];
    const float* kg_b    = (const float*)d_in[4];
    const float* gamma   = (const float*)d_in[5];
    const float* bias    = (const float*)d_in[6];
    const float* value_w = (const float*)d_in[7];
    float* out = (float*)d_out;

    static int smem_set = 0;
    if (!smem_set) {
        cudaFuncSetAttribute(k_conv, cudaFuncAttributeMaxDynamicSharedMemorySize,
                             SMF * 4);
        smem_set = 1;
    }

    k_mean<<<BB * CI, 256>>>(x);
    k_gen<<<BB * CO, 192>>>(ctx_w, ctx_b, kg_w, kg_b, gamma, value_w);
    dim3 grid(HH / 2, BB);   // (row band of 2, batch)
    k_conv<<<grid, 256, SMF * 4>>>(x, bias, out);
}

// round 10
// speedup vs baseline: 2.1057x; 1.0863x over previous
#include <cuda_runtime.h>
#include <math.h>
#include <cstdint>

#define BB   8
#define CI   64
#define CO   64
#define HH   128
#define WW   128
#define CTXC 16
#define FF   576
#define HWSZ (HH*WW)

// conv smem layout (floats)
#define XROW 140                    // 130 valid cols + pad; 6*140 % 32 == 8 -> conflict-free
#define XCH  (16*6*XROW)            // 13440 floats per x chunk (16 ch x 6 rows)
#define WROW 72                     // 64 o + pad (72 % 32 = 8)
#define WCH  (9*16*WROW)            // 10368 floats per W chunk
#define SMF  (2*XCH + 2*WCH)        // 47616 floats = 190464 B
#define WS0  (2*XCH)
#define NT   512                    // conv threads

// ---- device scratch ----
__device__ float g_meanx[BB * CI];
__device__ __align__(16) float g_wt[BB * 9 * CI * CO];    // [b][tap][cin][o], tf32
__device__ __align__(16) uint32_t g_xtf[(size_t)BB * CI * HWSZ];  // x, tf32-rounded

__device__ __forceinline__ uint32_t tf32_rna(float v) {
    uint32_t u; asm("cvt.rna.tf32.f32 %0, %1;" : "=r"(u) : "f"(v)); return u;
}
// cp-size 4; src-size = pred?4:0 (zero-fills dst when pred false -> image padding)
__device__ __forceinline__ void cp_async4(uint32_t dst, const void* src, bool pred) {
    int sz = pred ? 4 : 0;
    asm volatile("cp.async.ca.shared.global [%0], [%1], 4, %2;"
                 :: "r"(dst), "l"(src), "r"(sz));
}
__device__ __forceinline__ void cp_async16(uint32_t dst, const void* src) {
    asm volatile("cp.async.cg.shared.global [%0], [%1], 16;" :: "r"(dst), "l"(src));
}
__device__ __forceinline__ void cp_commit() { asm volatile("cp.async.commit_group;"); }

// ======= kernel 1: spatial mean of x -> (B,C)  +  tf32-rounded copy of x =======
__global__ void k_mean(const float* __restrict__ x) {
    int bc = blockIdx.x;
    const float4* p4 = (const float4*)(x + (size_t)bc * HWSZ);
    uint4* q4 = (uint4*)(g_xtf + (size_t)bc * HWSZ);
    float s = 0.f;
    for (int i = threadIdx.x; i < HWSZ / 4; i += 256) {
        float4 v = p4[i];
        s += (v.x + v.y) + (v.z + v.w);
        uint4 u;
        u.x = tf32_rna(v.x); u.y = tf32_rna(v.y);
        u.z = tf32_rna(v.z); u.w = tf32_rna(v.w);
        q4[i] = u;
    }
    __shared__ float red[8];
#pragma unroll
    for (int o = 16; o; o >>= 1) s += __shfl_xor_sync(0xffffffffu, s, o);
    if ((threadIdx.x & 31) == 0) red[threadIdx.x >> 5] = s;
    __syncthreads();
    if (threadIdx.x < 8) {
        s = red[threadIdx.x];
#pragma unroll
        for (int o = 4; o; o >>= 1) s += __shfl_xor_sync(0xffu, s, o);
        if (threadIdx.x == 0) g_meanx[bc] = s * (1.f / (float)HWSZ);
    }
}

// == kernel 2: generate kernels, center, fold value_w -> g_wt (tf32-rounded) ==
__global__ void k_gen(const float* __restrict__ ctx_w, const float* __restrict__ ctx_b,
                      const float* __restrict__ kg_w, const float* __restrict__ kg_b,
                      const float* __restrict__ gamma, const float* __restrict__ value_w) {
    int bo = blockIdx.x;          // 0..511
    int b = bo >> 6, o = bo & 63;
    __shared__ float ctx_s[CTXC];
    __shared__ float kern_s[FF];
    __shared__ float vw_s[CI * CI];
    __shared__ float red[6];
    int t = threadIdx.x;          // 0..191
    if (t < CTXC) {
        float s = ctx_b[t];
#pragma unroll 8
        for (int c = 0; c < CI; c++) s += ctx_w[t * CI + c] * g_meanx[b * CI + c];
        ctx_s[t] = s;
    }
    for (int i = t; i < CI * CI; i += 192) vw_s[i] = value_w[i];
    __syncthreads();

    float part = 0.f;
#pragma unroll
    for (int i = 0; i < 3; i++) {
        int f = t + 192 * i;                       // = c*9 + kk, kk = kh*3+kw
        const float4* wr = (const float4*)(kg_w + (size_t)(o * FF + f) * 16);
        float s = kg_b[o * FF + f];
#pragma unroll
        for (int jj = 0; jj < 4; jj++) {
            float4 w = wr[jj];
            s += ctx_s[4 * jj + 0] * w.x + ctx_s[4 * jj + 1] * w.y
               + ctx_s[4 * jj + 2] * w.z + ctx_s[4 * jj + 3] * w.w;
        }
        s = tanhf(s);
        kern_s[f] = s;
        part += s;
    }
#pragma unroll
    for (int off = 16; off; off >>= 1) part += __shfl_xor_sync(0xffffffffu, part, off);
    if ((t & 31) == 0) red[t >> 5] = part;
    __syncthreads();
    float total = red[0] + red[1] + red[2] + red[3] + red[4] + red[5];
    float lam = 1.f / (1.f + __expf(-gamma[o]));
    float sub = lam * total * (1.f / (float)FF);

    // W_eff[o][cin][kk] = sum_cp (kern[cp][kk] - sub) * value_w[cp][cin]
#pragma unroll
    for (int i = 0; i < 3; i++) {
        int f = t + 192 * i;
        int cin = f / 9, kk = f % 9;    // tap = kh*3 + kw
        float s = 0.f;
#pragma unroll 16
        for (int cp = 0; cp < CI; cp++)
            s += (kern_s[cp * 9 + kk] - sub) * vw_s[cp * CI + cin];
        ((uint32_t*)g_wt)[(((size_t)b * 9 + kk) * CI + cin) * CO + o] = tf32_rna(s);
    }
}

// ======== kernel 3: conv via mma.sync m16n8k8 tf32 (implicit GEMM) ========
// CTA 512 thr (16 warps): 64 o x 4 rows x 128 cols. warp = (mi = wid&3, rowi = wid>>2).
// K = 576 in 4 chunks of 16ch x 9 taps; double-buffered cp.async; operands pre-tf32.
__device__ __forceinline__ void load_chunk(uint32_t sb, int b, int kc, int y0,
                                           int buf, int t) {
    // x part: 16 ch x 6 rows x 130 cols (halo), zero-fill padding; src already tf32
    uint32_t xd = sb + (uint32_t)(buf * XCH) * 4u;
    const uint32_t* xb = g_xtf + ((size_t)(b * CI + kc * 16)) * HWSZ;
#pragma unroll
    for (int i = 0; i < 25; i++) {
        int e = t + NT * i;
        if (e < 16 * 6 * 130) {
            int c = e / 780;
            int rem = e - c * 780;
            int r = rem / 130;
            int j = rem - r * 130;
            int gy = y0 - 1 + r, gx = j - 1;
            bool ok = (gy >= 0) && (gy < HH) && (gx >= 0) && (gx < WW);
            const uint32_t* src = xb + (size_t)c * HWSZ + (ok ? gy : 0) * WW + (ok ? gx : 0);
            cp_async4(xd + (uint32_t)(((c * 6 + r) * XROW + j) * 4), src, ok);
        }
    }
    // W part: 9 taps x 16 c x 64 o, rows padded to 72
    uint32_t wd = sb + (uint32_t)(WS0 + buf * WCH) * 4u;
    const float* wb = g_wt + ((size_t)b * 9) * CI * CO;
#pragma unroll
    for (int i = 0; i < 5; i++) {
        int v = t + NT * i;           // 0..2303 (9*16*16)
        if (v < 2304) {
            int tap = v >> 8;
            int rem = v & 255;
            int cl = rem >> 4, o4 = rem & 15;
            const void* src = wb + ((size_t)tap * CI + kc * 16 + cl) * CO + o4 * 4;
            cp_async16(wd + (uint32_t)(((tap * 16 + cl) * WROW + o4 * 4) * 4), src);
        }
    }
}

__global__ void __launch_bounds__(NT, 1)
k_conv(const float* __restrict__ bias, float* __restrict__ out) {
    extern __shared__ __align__(16) float smem[];
    uint32_t sb = (uint32_t)__cvta_generic_to_shared(smem);
    int t = threadIdx.x;
    int lane = t & 31, wid = t >> 5;
    int mi = wid & 3, rowi = wid >> 2;     // mi: o strip, rowi: 0..3
    int o_base = mi * 16;
    int l4 = lane & 3, l2 = lane >> 2;
    int b = blockIdx.y, band = blockIdx.x;
    int y0 = band * 4;
    int y = y0 + rowi;

    float acc[16][4];
#pragma unroll
    for (int n = 0; n < 16; n++)
#pragma unroll
        for (int i = 0; i < 4; i++) acc[n][i] = 0.f;

    load_chunk(sb, b, 0, y0, 0, t);
    cp_commit();

    for (int kc = 0; kc < 4; kc++) {
        if (kc < 3) {
            load_chunk(sb, b, kc + 1, y0, (kc + 1) & 1, t);
            cp_commit();
            asm volatile("cp.async.wait_group 1;");
        } else {
            asm volatile("cp.async.wait_group 0;");
        }
        __syncthreads();

        const uint32_t* xs = (const uint32_t*)smem + (kc & 1) * XCH;
        const uint32_t* ws = (const uint32_t*)smem + WS0 + (kc & 1) * WCH;

        for (int tap = 0; tap < 9; tap++) {
            int kh = tap / 3, kw = tap % 3;
#pragma unroll
            for (int h = 0; h < 2; h++) {
                const uint32_t* wp = ws + (tap * 16 + h * 8 + l4) * WROW + o_base + l2;
                uint32_t a0 = wp[0];
                uint32_t a1 = wp[8];
                uint32_t a2 = wp[4 * WROW];
                uint32_t a3 = wp[4 * WROW + 8];
                const uint32_t* xp = xs + ((h * 8 + l4) * 6 + rowi + kh) * XROW + l2 + kw;
                const uint32_t* xq = xp + 4 * 6 * XROW;   // +4 channel planes
#pragma unroll
                for (int nt = 0; nt < 16; nt++) {
                    uint32_t b0 = xp[nt * 8];
                    uint32_t b1 = xq[nt * 8];
                    asm volatile(
                        "mma.sync.aligned.m16n8k8.row.col.f32.tf32.tf32.f32 "
                        "{%0,%1,%2,%3}, {%4,%5,%6,%7}, {%8,%9}, {%0,%1,%2,%3};"
                        : "+f"(acc[nt][0]), "+f"(acc[nt][1]),
                          "+f"(acc[nt][2]), "+f"(acc[nt][3])
                        : "r"(a0), "r"(a1), "r"(a2), "r"(a3), "r"(b0), "r"(b1));
                }
            }
        }
        __syncthreads();
    }

    // ---- epilogue: bias + relu ----
    int o = o_base + l2;
    float bz0 = bias[o], bz1 = bias[o + 8];
    float* r0 = out + (((size_t)b * CO + o) * HH + y) * WW;
    float* r1 = r0 + (size_t)8 * HH * WW;
#pragma unroll
    for (int nt = 0; nt < 16; nt++) {
        int col = nt * 8 + l4 * 2;
        float2 v0, v1;
        float u0 = acc[nt][0] + bz0, u1 = acc[nt][1] + bz0;
        float u2 = acc[nt][2] + bz1, u3 = acc[nt][3] + bz1;
        v0.x = u0 > 0.f ? u0 : 0.f;
        v0.y = u1 > 0.f ? u1 : 0.f;
        v1.x = u2 > 0.f ? u2 : 0.f;
        v1.y = u3 > 0.f ? u3 : 0.f;
        *(float2*)(r0 + col) = v0;
        *(float2*)(r1 + col) = v1;
    }
}

// ================================ launch ================================
extern "C" void kernel_launch(void* const* d_in, const int* in_sizes, int n_in,
                              void* d_out, int out_size) {
    const float* x       = (const float*)d_in[0];
    const float* ctx_w   = (const float*)d_in[1];
    const float* ctx_b   = (const float*)d_in[2];
    const float* kg_w    = (const float*)d_in[3];
    const float* kg_b    = (const float*)d_in[4];
    const float* gamma   = (const float*)d_in[5];
    const float* bias    = (const float*)d_in[6];
    const float* value_w = (const float*)d_in[7];
    float* out = (float*)d_out;

    static int smem_set = 0;
    if (!smem_set) {
        cudaFuncSetAttribute(k_conv, cudaFuncAttributeMaxDynamicSharedMemorySize,
                             SMF * 4);
        smem_set = 1;
    }

    k_mean<<<BB * CI, 256>>>(x);
    k_gen<<<BB * CO, 192>>>(ctx_w, ctx_b, kg_w, kg_b, gamma, value_w);
    dim3 grid(HH / 4, BB);   // (row band of 4, batch)
    k_conv<<<grid, NT, SMF * 4>>>(bias, out);
}

// round 11
// speedup vs baseline: 2.4704x; 1.1732x over previous
#include <cuda_runtime.h>
#include <cuda_fp16.h>
#include <math.h>
#include <cstdint>

#define BB   8
#define CI   64
#define CO   64
#define HH   128
#define WW   128
#define CTXC 16
#define FF   576
#define HWSZ (HH*WW)

// conv smem (bytes)
#define XBYTES (6*132*16*2)         // 25344: 6 rows x 132 cols x 16 ch halfs
#define WBYTES (9*64*16*2)          // 18432: 9 taps x 64 o x 16 ch halfs
#define SMEMB  (2*XBYTES + 2*WBYTES) // 87552
#define NT     512

// ---- device scratch ----
__device__ float g_meanx[BB * CI];
__device__ float g_rowsum[BB * CI * HH];
__device__ __align__(16) __half g_wt[(size_t)BB * 9 * CO * CI];       // [b][tap][o][c], x256
__device__ __align__(16) __half g_xh[(size_t)BB * HH * WW * CI];      // [b][y][x][c]

// cp.async 16B; src-size 0 zero-fills (image padding)
__device__ __forceinline__ void cp_async16z(uint32_t dst, const void* src, bool pred) {
    int sz = pred ? 16 : 0;
    asm volatile("cp.async.cg.shared.global [%0], [%1], 16, %2;"
                 :: "r"(dst), "l"(src), "r"(sz));
}
__device__ __forceinline__ void cp_commit() { asm volatile("cp.async.commit_group;"); }

// ======= kernel 1: transpose x -> fp16 [b][y][x][c], plus per-row channel sums =======
// grid (HH, BB), 256 threads
__global__ void k_xpose(const float* __restrict__ x) {
    __shared__ __half stage[128 * 66];      // [x][c], stride 66 halfs (conflict-free)
    __shared__ float psum[64 * 4];
    int t = threadIdx.x;
    int y = blockIdx.x, b = blockIdx.y;
    int xcol = t & 127, chalf = t >> 7;     // 2 channels per iteration
    int lane = t & 31;

    for (int c0 = 0; c0 < 64; c0 += 2) {
        int c = c0 + chalf;
        float v = x[(((size_t)(b * 64 + c)) * HH + y) * WW + xcol];
        stage[xcol * 66 + c] = __float2half_rn(v);
        // reduce over x within each warp (32 consecutive xcol)
        float s = v;
#pragma unroll
        for (int o = 16; o; o >>= 1) s += __shfl_xor_sync(0xffffffffu, s, o);
        if (lane == 0) psum[c * 4 + ((xcol >> 5) & 3)] = s;
    }
    __syncthreads();
    if (t < 64) {
        float rs = psum[t * 4] + psum[t * 4 + 1] + psum[t * 4 + 2] + psum[t * 4 + 3];
        g_rowsum[(b * 64 + t) * HH + y] = rs;
    }
    // write out: warp w handles x = w + 8k; lane j -> channels (2j, 2j+1)
    int w = t >> 5;
    uint32_t* dst = (uint32_t*)g_xh + (((size_t)b * HH + y) * WW) * 32;   // 64 halfs = 32 uints/px
#pragma unroll
    for (int k = 0; k < 16; k++) {
        int xx = w + 8 * k;
        uint32_t v = *(const uint32_t*)&stage[xx * 66 + 2 * lane];
        dst[(size_t)xx * 32 + lane] = v;
    }
}

// ======= kernel 1b: reduce row sums -> mean =======
__global__ void k_red() {
    int t = threadIdx.x;     // b*64 + c
    float s = 0.f;
#pragma unroll 8
    for (int y = 0; y < HH; y++) s += g_rowsum[t * HH + y];
    g_meanx[t] = s * (1.f / (float)HWSZ);
}

// == kernel 2: generate kernels, center, fold value_w -> g_wt (fp16, x256) ==
__global__ void k_gen(const float* __restrict__ ctx_w, const float* __restrict__ ctx_b,
                      const float* __restrict__ kg_w, const float* __restrict__ kg_b,
                      const float* __restrict__ gamma, const float* __restrict__ value_w) {
    int bo = blockIdx.x;          // 0..511
    int b = bo >> 6, o = bo & 63;
    __shared__ float ctx_s[CTXC];
    __shared__ float kern_s[FF];
    __shared__ float vw_s[CI * CI];
    __shared__ float red[6];
    int t = threadIdx.x;          // 0..191
    if (t < CTXC) {
        float s = ctx_b[t];
#pragma unroll 8
        for (int c = 0; c < CI; c++) s += ctx_w[t * CI + c] * g_meanx[b * CI + c];
        ctx_s[t] = s;
    }
    for (int i = t; i < CI * CI; i += 192) vw_s[i] = value_w[i];
    __syncthreads();

    float part = 0.f;
#pragma unroll
    for (int i = 0; i < 3; i++) {
        int f = t + 192 * i;                       // = c*9 + kk, kk = kh*3+kw
        const float4* wr = (const float4*)(kg_w + (size_t)(o * FF + f) * 16);
        float s = kg_b[o * FF + f];
#pragma unroll
        for (int jj = 0; jj < 4; jj++) {
            float4 w = wr[jj];
            s += ctx_s[4 * jj + 0] * w.x + ctx_s[4 * jj + 1] * w.y
               + ctx_s[4 * jj + 2] * w.z + ctx_s[4 * jj + 3] * w.w;
        }
        s = tanhf(s);
        kern_s[f] = s;
        part += s;
    }
#pragma unroll
    for (int off = 16; off; off >>= 1) part += __shfl_xor_sync(0xffffffffu, part, off);
    if ((t & 31) == 0) red[t >> 5] = part;
    __syncthreads();
    float total = red[0] + red[1] + red[2] + red[3] + red[4] + red[5];
    float lam = 1.f / (1.f + __expf(-gamma[o]));
    float sub = lam * total * (1.f / (float)FF);

    // W_eff[o][cin][kk] = sum_cp (kern[cp][kk] - sub) * value_w[cp][cin]; store x256 fp16
#pragma unroll
    for (int i = 0; i < 3; i++) {
        int f = t + 192 * i;
        int cin = f / 9, kk = f % 9;    // tap = kh*3 + kw
        float s = 0.f;
#pragma unroll 16
        for (int cp = 0; cp < CI; cp++)
            s += (kern_s[cp * 9 + kk] - sub) * vw_s[cp * CI + cin];
        g_wt[(((size_t)b * 9 + kk) * CO + o) * CI + cin] = __float2half_rn(s * 256.f);
    }
}

// ======== kernel 3: conv via mma.sync m16n8k16 fp16 (implicit GEMM) ========
// CTA 512 thr (16 warps): 64 o x 4 rows x 128 cols. warp = (mi = wid&3, rowi = wid>>2).
// K = 576 in 4 chunks of 16ch x 9 taps; k16 covers the whole chunk channel dim.
__device__ __forceinline__ void load_chunk(uint32_t sb, int b, int kc, int y0,
                                           int buf, int t) {
    // x: 6 rows x 130 cols, 32B (16ch) per pixel = 2 cp16
    uint32_t xd = sb + (uint32_t)buf * XBYTES;
    const char* xb = (const char*)g_xh;
#pragma unroll
    for (int i = 0; i < 4; i++) {
        int e = t + NT * i;            // 0..1559
        if (e < 1560) {
            int p = e >> 1, hh = e & 1;
            int r = p / 130, j = p - r * 130;
            int gy = y0 - 1 + r, gx = j - 1;
            bool ok = (gy >= 0) && (gy < HH) && (gx >= 0) && (gx < WW);
            const char* src = xb + ((((size_t)b * HH + (ok ? gy : 0)) * WW
                                     + (ok ? gx : 0)) * 64 + kc * 16) * 2 + hh * 16;
            cp_async16z(xd + (uint32_t)((r * 132 + j) * 32 + hh * 16), src, ok);
        }
    }
    // W: 9 taps x 64 o, 32B (16ch slice) per (tap,o) = 2 cp16
    uint32_t wd = sb + 2u * XBYTES + (uint32_t)buf * WBYTES;
    const char* wb = (const char*)g_wt + ((size_t)b * 9 * CO * CI + kc * 16) * 2;
#pragma unroll
    for (int i = 0; i < 3; i++) {
        int e = t + NT * i;            // 0..1151
        if (e < 1152) {
            int tap = e >> 7, rem = e & 127;
            int o = rem >> 1, hh = rem & 1;
            const char* src = wb + ((size_t)(tap * CO + o)) * (CI * 2) + hh * 16;
            cp_async16z(wd + (uint32_t)((tap * 64 + o) * 32 + hh * 16), src, true);
        }
    }
}

__global__ void __launch_bounds__(NT, 1)
k_conv(const float* __restrict__ bias, float* __restrict__ out) {
    extern __shared__ __align__(16) char smem[];
    uint32_t sb = (uint32_t)__cvta_generic_to_shared(smem);
    int t = threadIdx.x;
    int lane = t & 31, wid = t >> 5;
    int mi = wid & 3, rowi = wid >> 2;     // o strip, out row
    int o_base = mi * 16;
    int l4 = lane & 3, l2 = lane >> 2;
    int b = blockIdx.y, band = blockIdx.x;
    int y0 = band * 4;
    int y = y0 + rowi;

    float acc[16][4];
#pragma unroll
    for (int n = 0; n < 16; n++)
#pragma unroll
        for (int i = 0; i < 4; i++) acc[n][i] = 0.f;

    load_chunk(sb, b, 0, y0, 0, t);
    cp_commit();

    for (int kc = 0; kc < 4; kc++) {
        if (kc < 3) {
            load_chunk(sb, b, kc + 1, y0, (kc + 1) & 1, t);
            cp_commit();
            asm volatile("cp.async.wait_group 1;");
        } else {
            asm volatile("cp.async.wait_group 0;");
        }
        __syncthreads();

        const uint32_t* xs = (const uint32_t*)(smem + (kc & 1) * XBYTES);
        const uint32_t* ws = (const uint32_t*)(smem + 2 * XBYTES + (kc & 1) * WBYTES);

        for (int tap = 0; tap < 9; tap++) {
            int kh = tap / 3, kw = tap % 3;
            // A fragment: W[tap][o=o_base+l2(+8)][k=2*l4(+8..)] half2s
            const uint32_t* wp = ws + (tap * 64 + o_base + l2) * 8 + l4;
            uint32_t a0 = wp[0];        // (m=l2,   k=2*l4, 2*l4+1)
            uint32_t a1 = wp[64];       // (m=l2+8, same k)      (+8 rows * 8 uints)
            uint32_t a2 = wp[4];        // (m=l2,   k+8)
            uint32_t a3 = wp[68];       // (m=l2+8, k+8)
            // B fragment base: x[row=rowi+kh][col=l2+kw][k=2*l4]
            const uint32_t* xp = xs + ((rowi + kh) * 132 + l2 + kw) * 8 + l4;
#pragma unroll
            for (int nt = 0; nt < 16; nt++) {
                uint32_t b0 = xp[nt * 64];        // 8 cols * 8 uints
                uint32_t b1 = xp[nt * 64 + 4];    // k+8
                asm volatile(
                    "mma.sync.aligned.m16n8k16.row.col.f32.f16.f16.f32 "
                    "{%0,%1,%2,%3}, {%4,%5,%6,%7}, {%8,%9}, {%0,%1,%2,%3};"
                    : "+f"(acc[nt][0]), "+f"(acc[nt][1]),
                      "+f"(acc[nt][2]), "+f"(acc[nt][3])
                    : "r"(a0), "r"(a1), "r"(a2), "r"(a3), "r"(b0), "r"(b1));
            }
        }
        __syncthreads();
    }

    // ---- epilogue: un-scale (W was x256), bias, relu ----
    const float inv = 1.f / 256.f;
    int o = o_base + l2;
    float bz0 = bias[o], bz1 = bias[o + 8];
    float* r0 = out + (((size_t)b * CO + o) * HH + y) * WW;
    float* r1 = r0 + (size_t)8 * HH * WW;
#pragma unroll
    for (int nt = 0; nt < 16; nt++) {
        int col = nt * 8 + l4 * 2;
        float2 v0, v1;
        float u0 = fmaf(acc[nt][0], inv, bz0), u1 = fmaf(acc[nt][1], inv, bz0);
        float u2 = fmaf(acc[nt][2], inv, bz1), u3 = fmaf(acc[nt][3], inv, bz1);
        v0.x = u0 > 0.f ? u0 : 0.f;
        v0.y = u1 > 0.f ? u1 : 0.f;
        v1.x = u2 > 0.f ? u2 : 0.f;
        v1.y = u3 > 0.f ? u3 : 0.f;
        *(float2*)(r0 + col) = v0;
        *(float2*)(r1 + col) = v1;
    }
}

// ================================ launch ================================
extern "C" void kernel_launch(void* const* d_in, const int* in_sizes, int n_in,
                              void* d_out, int out_size) {
    const float* x       = (const float*)d_in[0];
    const float* ctx_w   = (const float*)d_in[1];
    const float* ctx_b   = (const float*)d_in[2];
    const float* kg_w    = (const float*)d_in[3];
    const float* kg_b    = (const float*)d_in[4];
    const float* gamma   = (const float*)d_in[5];
    const float* bias    = (const float*)d_in[6];
    const float* value_w = (const float*)d_in[7];
    float* out = (float*)d_out;

    static int smem_set = 0;
    if (!smem_set) {
        cudaFuncSetAttribute(k_conv, cudaFuncAttributeMaxDynamicSharedMemorySize, SMEMB);
        smem_set = 1;
    }

    dim3 gx(HH, BB);
    k_xpose<<<gx, 256>>>(x);
    k_red<<<1, BB * CI>>>();
    k_gen<<<BB * CO, 192>>>(ctx_w, ctx_b, kg_w, kg_b, gamma, value_w);
    dim3 grid(HH / 4, BB);   // (row band of 4, batch)
    k_conv<<<grid, NT, SMEMB>>>(bias, out);
}

// round 12
// speedup vs baseline: 2.9283x; 1.1853x over previous
#include <cuda_runtime.h>
#include <cuda_fp16.h>
#include <math.h>
#include <cstdint>

#define BB   8
#define CI   64
#define CO   64
#define HH   128
#define WW   128
#define CTXC 16
#define FF   576
#define HWSZ (HH*WW)

// conv smem (bytes) — 48B stride per 16-ch slice (32B payload + 16B pad)
#define CSTRIDE 48
#define XROWB  (132*CSTRIDE)          // 6336 B per halo row
#define XBYTES (6*XROWB)              // 38016
#define WBYTES (9*64*CSTRIDE)         // 27648
#define SMEMB  (2*XBYTES + 2*WBYTES)  // 131328
#define NT     512

// ---- device scratch ----
__device__ float g_meanx[BB * CI];
__device__ float g_rowsum[BB * CI * HH];
__device__ __align__(16) __half g_wt[(size_t)BB * 9 * CO * CI];   // [b][tap][o][c], x256
__device__ __align__(16) __half g_xh[(size_t)BB * HH * WW * CI];  // [b][y][x][c]

__device__ __forceinline__ void cp_async16z(uint32_t dst, const void* src, bool pred) {
    int sz = pred ? 16 : 0;
    asm volatile("cp.async.cg.shared.global [%0], [%1], 16, %2;"
                 :: "r"(dst), "l"(src), "r"(sz));
}
__device__ __forceinline__ void cp_commit() { asm volatile("cp.async.commit_group;"); }

// ======= kernel 1: transpose x -> fp16 [b][y][x][c], plus per-row channel sums =======
__global__ void k_xpose(const float* __restrict__ x) {
    __shared__ __half stage[128 * 66];
    __shared__ float psum[64 * 4];
    int t = threadIdx.x;
    int y = blockIdx.x, b = blockIdx.y;
    int xcol = t & 127, chalf = t >> 7;
    int lane = t & 31;

    for (int c0 = 0; c0 < 64; c0 += 2) {
        int c = c0 + chalf;
        float v = x[(((size_t)(b * 64 + c)) * HH + y) * WW + xcol];
        stage[xcol * 66 + c] = __float2half_rn(v);
        float s = v;
#pragma unroll
        for (int o = 16; o; o >>= 1) s += __shfl_xor_sync(0xffffffffu, s, o);
        if (lane == 0) psum[c * 4 + ((xcol >> 5) & 3)] = s;
    }
    __syncthreads();
    if (t < 64) {
        float rs = psum[t * 4] + psum[t * 4 + 1] + psum[t * 4 + 2] + psum[t * 4 + 3];
        g_rowsum[(b * 64 + t) * HH + y] = rs;
    }
    int w = t >> 5;
    uint32_t* dst = (uint32_t*)g_xh + (((size_t)b * HH + y) * WW) * 32;
#pragma unroll
    for (int k = 0; k < 16; k++) {
        int xx = w + 8 * k;
        uint32_t v = *(const uint32_t*)&stage[xx * 66 + 2 * lane];
        dst[(size_t)xx * 32 + lane] = v;
    }
}

// ======= kernel 1b: reduce row sums -> mean =======
__global__ void k_red() {
    int t = threadIdx.x;
    float s = 0.f;
#pragma unroll 8
    for (int y = 0; y < HH; y++) s += g_rowsum[t * HH + y];
    g_meanx[t] = s * (1.f / (float)HWSZ);
}

// == kernel 2: generate kernels, center, fold value_w -> g_wt (fp16, x256) ==
__global__ void k_gen(const float* __restrict__ ctx_w, const float* __restrict__ ctx_b,
                      const float* __restrict__ kg_w, const float* __restrict__ kg_b,
                      const float* __restrict__ gamma, const float* __restrict__ value_w) {
    int bo = blockIdx.x;
    int b = bo >> 6, o = bo & 63;
    __shared__ float ctx_s[CTXC];
    __shared__ float kern_s[FF];
    __shared__ float vw_s[CI * CI];
    __shared__ float red[6];
    int t = threadIdx.x;
    if (t < CTXC) {
        float s = ctx_b[t];
#pragma unroll 8
        for (int c = 0; c < CI; c++) s += ctx_w[t * CI + c] * g_meanx[b * CI + c];
        ctx_s[t] = s;
    }
    for (int i = t; i < CI * CI; i += 192) vw_s[i] = value_w[i];
    __syncthreads();

    float part = 0.f;
#pragma unroll
    for (int i = 0; i < 3; i++) {
        int f = t + 192 * i;
        const float4* wr = (const float4*)(kg_w + (size_t)(o * FF + f) * 16);
        float s = kg_b[o * FF + f];
#pragma unroll
        for (int jj = 0; jj < 4; jj++) {
            float4 w = wr[jj];
            s += ctx_s[4 * jj + 0] * w.x + ctx_s[4 * jj + 1] * w.y
               + ctx_s[4 * jj + 2] * w.z + ctx_s[4 * jj + 3] * w.w;
        }
        s = tanhf(s);
        kern_s[f] = s;
        part += s;
    }
#pragma unroll
    for (int off = 16; off; off >>= 1) part += __shfl_xor_sync(0xffffffffu, part, off);
    if ((t & 31) == 0) red[t >> 5] = part;
    __syncthreads();
    float total = red[0] + red[1] + red[2] + red[3] + red[4] + red[5];
    float lam = 1.f / (1.f + __expf(-gamma[o]));
    float sub = lam * total * (1.f / (float)FF);

#pragma unroll
    for (int i = 0; i < 3; i++) {
        int f = t + 192 * i;
        int cin = f / 9, kk = f % 9;
        float s = 0.f;
#pragma unroll 16
        for (int cp = 0; cp < CI; cp++)
            s += (kern_s[cp * 9 + kk] - sub) * vw_s[cp * CI + cin];
        g_wt[(((size_t)b * 9 + kk) * CO + o) * CI + cin] = __float2half_rn(s * 256.f);
    }
}

// ======== kernel 3: conv via mma.sync m16n8k16 fp16 + ldmatrix B ========
__device__ __forceinline__ void load_chunk(uint32_t sb, int b, int kc, int y0,
                                           int buf, int t) {
    uint32_t xd = sb + (uint32_t)buf * XBYTES;
    const char* xb = (const char*)g_xh;
#pragma unroll
    for (int i = 0; i < 4; i++) {
        int e = t + NT * i;            // 0..1559 (6*130*2)
        if (e < 1560) {
            int p = e >> 1, hh = e & 1;
            int r = p / 130, j = p - r * 130;
            int gy = y0 - 1 + r, gx = j - 1;
            bool ok = (gy >= 0) && (gy < HH) && (gx >= 0) && (gx < WW);
            const char* src = xb + ((((size_t)b * HH + (ok ? gy : 0)) * WW
                                     + (ok ? gx : 0)) * 64 + kc * 16) * 2 + hh * 16;
            cp_async16z(xd + (uint32_t)(r * XROWB + j * CSTRIDE + hh * 16), src, ok);
        }
    }
    uint32_t wd = sb + 2u * XBYTES + (uint32_t)buf * WBYTES;
    const char* wb = (const char*)g_wt + ((size_t)b * 9 * CO * CI + kc * 16) * 2;
#pragma unroll
    for (int i = 0; i < 3; i++) {
        int e = t + NT * i;            // 0..1151 (9*64*2)
        if (e < 1152) {
            int tap = e >> 7, rem = e & 127;
            int o = rem >> 1, hh = rem & 1;
            const char* src = wb + ((size_t)(tap * CO + o)) * (CI * 2) + hh * 16;
            cp_async16z(wd + (uint32_t)((tap * 64 + o) * CSTRIDE + hh * 16), src, true);
        }
    }
}

__global__ void __launch_bounds__(NT, 1)
k_conv(const float* __restrict__ bias, float* __restrict__ out) {
    extern __shared__ __align__(16) char smem[];
    uint32_t sb = (uint32_t)__cvta_generic_to_shared(smem);
    int t = threadIdx.x;
    int lane = t & 31, wid = t >> 5;
    int mi = wid & 3, rowi = wid >> 2;
    int o_base = mi * 16;
    int l4 = lane & 3, l2 = lane >> 2;
    int b = blockIdx.y, band = blockIdx.x;
    int y0 = band * 4;
    int y = y0 + rowi;

    // per-lane ldmatrix row address component: tile = lane>>3, row-in-tile = lane&7
    int tile = lane >> 3, rr = lane & 7;
    int nn = ((tile >> 1) << 3) + rr;                    // n within 16-col group
    uint32_t bxoff = (uint32_t)(nn * CSTRIDE + (tile & 1) * 16);

    float acc[16][4];
#pragma unroll
    for (int n = 0; n < 16; n++)
#pragma unroll
        for (int i = 0; i < 4; i++) acc[n][i] = 0.f;

    load_chunk(sb, b, 0, y0, 0, t);
    cp_commit();

    for (int kc = 0; kc < 4; kc++) {
        if (kc < 3) {
            load_chunk(sb, b, kc + 1, y0, (kc + 1) & 1, t);
            cp_commit();
            asm volatile("cp.async.wait_group 1;");
        } else {
            asm volatile("cp.async.wait_group 0;");
        }
        __syncthreads();

        uint32_t xsb = sb + (uint32_t)(kc & 1) * XBYTES;
        const uint32_t* ws = (const uint32_t*)(smem + 2 * XBYTES + (kc & 1) * WBYTES);

        for (int tap = 0; tap < 9; tap++) {
            int kh = tap / 3, kw = tap % 3;
            // A fragment (scalar LDS, stride-12 conflict-free)
            const uint32_t* wp = ws + (tap * 64 + o_base + l2) * 12 + l4;
            uint32_t a0 = wp[0];
            uint32_t a1 = wp[96];
            uint32_t a2 = wp[4];
            uint32_t a3 = wp[100];
            uint32_t rowb = xsb + (uint32_t)((rowi + kh) * XROWB + kw * CSTRIDE) + bxoff;
#pragma unroll
            for (int g = 0; g < 8; g++) {
                uint32_t addr = rowb + (uint32_t)(g * 16 * CSTRIDE);
                uint32_t b0, b1, b2, b3;
                asm volatile(
                    "ldmatrix.sync.aligned.m8n8.x4.shared.b16 {%0,%1,%2,%3}, [%4];"
                    : "=r"(b0), "=r"(b1), "=r"(b2), "=r"(b3) : "r"(addr));
                asm volatile(
                    "mma.sync.aligned.m16n8k16.row.col.f32.f16.f16.f32 "
                    "{%0,%1,%2,%3}, {%4,%5,%6,%7}, {%8,%9}, {%0,%1,%2,%3};"
                    : "+f"(acc[2*g][0]), "+f"(acc[2*g][1]),
                      "+f"(acc[2*g][2]), "+f"(acc[2*g][3])
                    : "r"(a0), "r"(a1), "r"(a2), "r"(a3), "r"(b0), "r"(b1));
                asm volatile(
                    "mma.sync.aligned.m16n8k16.row.col.f32.f16.f16.f32 "
                    "{%0,%1,%2,%3}, {%4,%5,%6,%7}, {%8,%9}, {%0,%1,%2,%3};"
                    : "+f"(acc[2*g+1][0]), "+f"(acc[2*g+1][1]),
                      "+f"(acc[2*g+1][2]), "+f"(acc[2*g+1][3])
                    : "r"(a0), "r"(a1), "r"(a2), "r"(a3), "r"(b2), "r"(b3));
            }
        }
        __syncthreads();
    }

    // ---- epilogue: un-scale (W was x256), bias, relu ----
    const float inv = 1.f / 256.f;
    int o = o_base + l2;
    float bz0 = bias[o], bz1 = bias[o + 8];
    float* r0 = out + (((size_t)b * CO + o) * HH + y) * WW;
    float* r1 = r0 + (size_t)8 * HH * WW;
#pragma unroll
    for (int nt = 0; nt < 16; nt++) {
        int col = nt * 8 + l4 * 2;
        float2 v0, v1;
        float u0 = fmaf(acc[nt][0], inv, bz0), u1 = fmaf(acc[nt][1], inv, bz0);
        float u2 = fmaf(acc[nt][2], inv, bz1), u3 = fmaf(acc[nt][3], inv, bz1);
        v0.x = u0 > 0.f ? u0 : 0.f;
        v0.y = u1 > 0.f ? u1 : 0.f;
        v1.x = u2 > 0.f ? u2 : 0.f;
        v1.y = u3 > 0.f ? u3 : 0.f;
        *(float2*)(r0 + col) = v0;
        *(float2*)(r1 + col) = v1;
    }
}

// ================================ launch ================================
extern "C" void kernel_launch(void* const* d_in, const int* in_sizes, int n_in,
                              void* d_out, int out_size) {
    const float* x       = (const float*)d_in[0];
    const float* ctx_w   = (const float*)d_in[1];
    const float* ctx_b   = (const float*)d_in[2];
    const float* kg_w    = (const float*)d_in[3];
    const float* kg_b    = (const float*)d_in[4];
    const float* gamma   = (const float*)d_in[5];
    const float* bias    = (const float*)d_in[6];
    const float* value_w = (const float*)d_in[7];
    float* out = (float*)d_out;

    static int smem_set = 0;
    if (!smem_set) {
        cudaFuncSetAttribute(k_conv, cudaFuncAttributeMaxDynamicSharedMemorySize, SMEMB);
        smem_set = 1;
    }

    dim3 gx(HH, BB);
    k_xpose<<<gx, 256>>>(x);
    k_red<<<1, BB * CI>>>();
    k_gen<<<BB * CO, 192>>>(ctx_w, ctx_b, kg_w, kg_b, gamma, value_w);
    dim3 grid(HH / 4, BB);   // (row band of 4, batch)
    k_conv<<<grid, NT, SMEMB>>>(bias, out);
}

// round 16
// speedup vs baseline: 4.4233x; 1.5105x over previous
#include <cuda_runtime.h>
#include <cuda_fp16.h>
#include <math.h>
#include <cstdint>

#define BB   8
#define CI   64
#define CO   64
#define HH   128
#define WW   128
#define CTXC 16
#define FF   576
#define HWSZ (HH*WW)

// conv smem (bytes) — 48B stride per 16-ch slice (32B payload + 16B pad)
#define CSTRIDE 48
#define XROWB  (132*CSTRIDE)          // 6336 B per halo row
#define XBYTES (6*XROWB)              // 38016
#define WBYTES (9*64*CSTRIDE)         // 27648
#define SMEMB  (2*XBYTES + 2*WBYTES)  // 131328
#define NT     512

// ---- device scratch ----
__device__ float g_meanx[BB * CI];
__device__ float g_rowsum[HH * BB * CI];   // [y][b*64+c]
__device__ __align__(16) __half g_wt[(size_t)BB * 9 * CO * CI];   // [b][tap][o][c], x256
__device__ __align__(16) __half g_xh[(size_t)BB * HH * WW * CI];  // [b][y][x][c]

__device__ __forceinline__ void cp_async16z(uint32_t dst, const void* src, bool pred) {
    int sz = pred ? 16 : 0;
    asm volatile("cp.async.cg.shared.global [%0], [%1], 16, %2;"
                 :: "r"(dst), "l"(src), "r"(sz));
}
__device__ __forceinline__ void cp_commit() { asm volatile("cp.async.commit_group;"); }

// ======= kernel 1: transpose x -> fp16 [b][y][x][c], plus per-row channel sums =======
__global__ void k_xpose(const float* __restrict__ x) {
    __shared__ __half stage[128 * 66];
    __shared__ float psum[64 * 2];
    int t = threadIdx.x;
    int y = blockIdx.x, b = blockIdx.y;
    int xcol = t & 127, chalf = t >> 7;

#pragma unroll
    for (int c0 = 0; c0 < 64; c0 += 2) {
        int c = c0 + chalf;
        float v = x[(((size_t)(b * 64 + c)) * HH + y) * WW + xcol];
        stage[xcol * 66 + c] = __float2half_rn(v);
    }
    __syncthreads();
    // row sums from staged tile (no shfl): 128 threads, each sums 64 x-positions
    if (t < 128) {
        int c = t & 63, h = t >> 6;
        float s = 0.f;
#pragma unroll 8
        for (int xx = 64 * h; xx < 64 * h + 64; xx++)
            s += __half2float(stage[xx * 66 + c]);
        psum[c * 2 + h] = s;
    }
    __syncthreads();
    if (t < 64)
        g_rowsum[y * (BB * CI) + b * 64 + t] = psum[t * 2] + psum[t * 2 + 1];

    // write out: warp w handles x = w + 8k; lane j -> channels (2j, 2j+1)
    int w = t >> 5, lane = t & 31;
    uint32_t* dst = (uint32_t*)g_xh + (((size_t)b * HH + y) * WW) * 32;
#pragma unroll
    for (int k = 0; k < 16; k++) {
        int xx = w + 8 * k;
        uint32_t v = *(const uint32_t*)&stage[xx * 66 + 2 * lane];
        dst[(size_t)xx * 32 + lane] = v;
    }
}

// ======= kernel 1b: reduce row sums -> mean (coalesced) =======
__global__ void k_red() {
    int t = threadIdx.x;     // 0..511 = b*64+c
    float s = 0.f;
#pragma unroll 8
    for (int y = 0; y < HH; y++) s += g_rowsum[y * (BB * CI) + t];
    g_meanx[t] = s * (1.f / (float)HWSZ);
}

// == kernel 2: generate kernels, center, fold value_w -> g_wt (fp16, x256) ==
__global__ void k_gen(const float* __restrict__ ctx_w, const float* __restrict__ ctx_b,
                      const float* __restrict__ kg_w, const float* __restrict__ kg_b,
                      const float* __restrict__ gamma, const float* __restrict__ value_w) {
    int bo = blockIdx.x;
    int b = bo >> 6, o = bo & 63;
    __shared__ float ctx_s[CTXC];
    __shared__ float kern_s[FF];
    __shared__ float vw_s[CI * CI];
    __shared__ float red[6];
    int t = threadIdx.x;
    if (t < CTXC) {
        float s = ctx_b[t];
#pragma unroll 8
        for (int c = 0; c < CI; c++) s += ctx_w[t * CI + c] * g_meanx[b * CI + c];
        ctx_s[t] = s;
    }
    for (int i = t; i < CI * CI; i += 192) vw_s[i] = value_w[i];
    __syncthreads();

    float part = 0.f;
#pragma unroll
    for (int i = 0; i < 3; i++) {
        int f = t + 192 * i;
        const float4* wr = (const float4*)(kg_w + (size_t)(o * FF + f) * 16);
        float s = kg_b[o * FF + f];
#pragma unroll
        for (int jj = 0; jj < 4; jj++) {
            float4 w = wr[jj];
            s += ctx_s[4 * jj + 0] * w.x + ctx_s[4 * jj + 1] * w.y
               + ctx_s[4 * jj + 2] * w.z + ctx_s[4 * jj + 3] * w.w;
        }
        s = tanhf(s);
        kern_s[f] = s;
        part += s;
    }
#pragma unroll
    for (int off = 16; off; off >>= 1) part += __shfl_xor_sync(0xffffffffu, part, off);
    if ((t & 31) == 0) red[t >> 5] = part;
    __syncthreads();
    float total = red[0] + red[1] + red[2] + red[3] + red[4] + red[5];
    float lam = 1.f / (1.f + __expf(-gamma[o]));
    float sub = lam * total * (1.f / (float)FF);

#pragma unroll
    for (int i = 0; i < 3; i++) {
        int f = t + 192 * i;
        int cin = f / 9, kk = f % 9;
        float s = 0.f;
#pragma unroll 16
        for (int cp = 0; cp < CI; cp++)
            s += (kern_s[cp * 9 + kk] - sub) * vw_s[cp * CI + cin];
        g_wt[(((size_t)b * 9 + kk) * CO + o) * CI + cin] = __float2half_rn(s * 256.f);
    }
}

// ======== kernel 3: conv via mma.sync m16n8k16 fp16 + ldmatrix B ========
// warp = (oHalf = wid&1, rowi = (wid>>1)&3, colHalf = wid>>3):
// 32 o x 1 row x 64 cols per warp -> 2 A-frags x 8 n-tiles, B LDSM shared by only 2 warps.
__device__ __forceinline__ void load_chunk(uint32_t sb, int b, int kc, int y0,
                                           int buf, int t) {
    uint32_t xd = sb + (uint32_t)buf * XBYTES;
    const char* xb = (const char*)g_xh;
#pragma unroll
    for (int i = 0; i < 4; i++) {
        int e = t + NT * i;            // 0..1559 (6*130*2)
        if (e < 1560) {
            int p = e >> 1, hh = e & 1;
            int r = p / 130, j = p - r * 130;
            int gy = y0 - 1 + r, gx = j - 1;
            bool ok = (gy >= 0) && (gy < HH) && (gx >= 0) && (gx < WW);
            const char* src = xb + ((((size_t)b * HH + (ok ? gy : 0)) * WW
                                     + (ok ? gx : 0)) * 64 + kc * 16) * 2 + hh * 16;
            cp_async16z(xd + (uint32_t)(r * XROWB + j * CSTRIDE + hh * 16), src, ok);
        }
    }
    uint32_t wd = sb + 2u * XBYTES + (uint32_t)buf * WBYTES;
    const char* wb = (const char*)g_wt + ((size_t)b * 9 * CO * CI + kc * 16) * 2;
#pragma unroll
    for (int i = 0; i < 3; i++) {
        int e = t + NT * i;            // 0..1151 (9*64*2)
        if (e < 1152) {
            int tap = e >> 7, rem = e & 127;
            int o = rem >> 1, hh = rem & 1;
            const char* src = wb + ((size_t)(tap * CO + o)) * (CI * 2) + hh * 16;
            cp_async16z(wd + (uint32_t)((tap * 64 + o) * CSTRIDE + hh * 16), src, true);
        }
    }
}

__global__ void __launch_bounds__(NT, 1)
k_conv(const float* __restrict__ bias, float* __restrict__ out) {
    extern __shared__ __align__(16) char smem[];
    uint32_t sb = (uint32_t)__cvta_generic_to_shared(smem);
    int t = threadIdx.x;
    int lane = t & 31, wid = t >> 5;
    int oHalf = wid & 1, rowi = (wid >> 1) & 3, colHalf = wid >> 3;
    int o_base = oHalf * 32;
    int col_base = colHalf * 64;
    int l4 = lane & 3, l2 = lane >> 2;
    int b = blockIdx.y, band = blockIdx.x;
    int y0 = band * 4;
    int y = y0 + rowi;

    // ldmatrix lane->row mapping: tile = lane>>3, row-in-tile = lane&7
    int tile = lane >> 3, rr = lane & 7;
    int nn = ((tile >> 1) << 3) + rr;
    uint32_t bxoff = (uint32_t)((col_base + nn) * CSTRIDE + (tile & 1) * 16);

    float acc[2][8][4];
#pragma unroll
    for (int s = 0; s < 2; s++)
#pragma unroll
        for (int n = 0; n < 8; n++)
#pragma unroll
            for (int i = 0; i < 4; i++) acc[s][n][i] = 0.f;

    load_chunk(sb, b, 0, y0, 0, t);
    cp_commit();

    for (int kc = 0; kc < 4; kc++) {
        if (kc < 3) {
            load_chunk(sb, b, kc + 1, y0, (kc + 1) & 1, t);
            cp_commit();
            asm volatile("cp.async.wait_group 1;");
        } else {
            asm volatile("cp.async.wait_group 0;");
        }
        __syncthreads();

        uint32_t xsb = sb + (uint32_t)(kc & 1) * XBYTES;
        const uint32_t* ws = (const uint32_t*)(smem + 2 * XBYTES + (kc & 1) * WBYTES);

        for (int tap = 0; tap < 9; tap++) {
            int kh = tap / 3, kw = tap % 3;
            // A fragments for both 16-o strips (stride-12 words, conflict-free)
            const uint32_t* wp0 = ws + (tap * 64 + o_base + l2) * 12 + l4;
            const uint32_t* wp1 = wp0 + 16 * 12;
            uint32_t a00 = wp0[0],  a01 = wp0[96],  a02 = wp0[4],  a03 = wp0[100];
            uint32_t a10 = wp1[0],  a11 = wp1[96],  a12 = wp1[4],  a13 = wp1[100];
            uint32_t rowb = xsb + (uint32_t)((rowi + kh) * XROWB + kw * CSTRIDE) + bxoff;
#pragma unroll
            for (int g = 0; g < 4; g++) {
                uint32_t addr = rowb + (uint32_t)(g * 16 * CSTRIDE);
                uint32_t b0, b1, b2, b3;
                asm volatile(
                    "ldmatrix.sync.aligned.m8n8.x4.shared.b16 {%0,%1,%2,%3}, [%4];"
                    : "=r"(b0), "=r"(b1), "=r"(b2), "=r"(b3) : "r"(addr));
                asm volatile(
                    "mma.sync.aligned.m16n8k16.row.col.f32.f16.f16.f32 "
                    "{%0,%1,%2,%3}, {%4,%5,%6,%7}, {%8,%9}, {%0,%1,%2,%3};"
                    : "+f"(acc[0][2*g][0]), "+f"(acc[0][2*g][1]),
                      "+f"(acc[0][2*g][2]), "+f"(acc[0][2*g][3])
                    : "r"(a00), "r"(a01), "r"(a02), "r"(a03), "r"(b0), "r"(b1));
                asm volatile(
                    "mma.sync.aligned.m16n8k16.row.col.f32.f16.f16.f32 "
                    "{%0,%1,%2,%3}, {%4,%5,%6,%7}, {%8,%9}, {%0,%1,%2,%3};"
                    : "+f"(acc[0][2*g+1][0]), "+f"(acc[0][2*g+1][1]),
                      "+f"(acc[0][2*g+1][2]), "+f"(acc[0][2*g+1][3])
                    : "r"(a00), "r"(a01), "r"(a02), "r"(a03), "r"(b2), "r"(b3));
                asm volatile(
                    "mma.sync.aligned.m16n8k16.row.col.f32.f16.f16.f32 "
                    "{%0,%1,%2,%3}, {%4,%5,%6,%7}, {%8,%9}, {%0,%1,%2,%3};"
                    : "+f"(acc[1][2*g][0]), "+f"(acc[1][2*g][1]),
                      "+f"(acc[1][2*g][2]), "+f"(acc[1][2*g][3])
                    : "r"(a10), "r"(a11), "r"(a12), "r"(a13), "r"(b0), "r"(b1));
                asm volatile(
                    "mma.sync.aligned.m16n8k16.row.col.f32.f16.f16.f32 "
                    "{%0,%1,%2,%3}, {%4,%5,%6,%7}, {%8,%9}, {%0,%1,%2,%3};"
                    : "+f"(acc[1][2*g+1][0]), "+f"(acc[1][2*g+1][1]),
                      "+f"(acc[1][2*g+1][2]), "+f"(acc[1][2*g+1][3])
                    : "r"(a10), "r"(a11), "r"(a12), "r"(a13), "r"(b2), "r"(b3));
            }
        }
        __syncthreads();
    }

    // ---- epilogue: un-scale (W was x256), bias, relu ----
    const float inv = 1.f / 256.f;
#pragma unroll
    for (int s = 0; s < 2; s++) {
        int o = o_base + s * 16 + l2;
        float bz0 = bias[o], bz1 = bias[o + 8];
        float* r0 = out + (((size_t)b * CO + o) * HH + y) * WW + col_base;
        float* r1 = r0 + (size_t)8 * HH * WW;
#pragma unroll
        for (int nt = 0; nt < 8; nt++) {
            int col = nt * 8 + l4 * 2;
            float2 v0, v1;
            float u0 = fmaf(acc[s][nt][0], inv, bz0), u1 = fmaf(acc[s][nt][1], inv, bz0);
            float u2 = fmaf(acc[s][nt][2], inv, bz1), u3 = fmaf(acc[s][nt][3], inv, bz1);
            v0.x = u0 > 0.f ? u0 : 0.f;
            v0.y = u1 > 0.f ? u1 : 0.f;
            v1.x = u2 > 0.f ? u2 : 0.f;
            v1.y = u3 > 0.f ? u3 : 0.f;
            *(float2*)(r0 + col) = v0;
            *(float2*)(r1 + col) = v1;
        }
    }
}

// ================================ launch ================================
extern "C" void kernel_launch(void* const* d_in, const int* in_sizes, int n_in,
                              void* d_out, int out_size) {
    const float* x       = (const float*)d_in[0];
    const float* ctx_w   = (const float*)d_in[1];
    const float* ctx_b   = (const float*)d_in[2];
    const float* kg_w    = (const float*)d_in[3];
    const float* kg_b    = (const float*)d_in[4];
    const float* gamma   = (const float*)d_in[5];
    const float* bias    = (const float*)d_in[6];
    const float* value_w = (const float*)d_in[7];
    float* out = (float*)d_out;

    static int smem_set = 0;
    if (!smem_set) {
        cudaFuncSetAttribute(k_conv, cudaFuncAttributeMaxDynamicSharedMemorySize, SMEMB);
        smem_set = 1;
    }

    dim3 gx(HH, BB);
    k_xpose<<<gx, 256>>>(x);
    k_red<<<1, BB * CI>>>();
    k_gen<<<BB * CO, 192>>>(ctx_w, ctx_b, kg_w, kg_b, gamma, value_w);
    dim3 grid(HH / 4, BB);   // (row band of 4, batch)
    k_conv<<<grid, NT, SMEMB>>>(bias, out);
}